// round 2
// baseline (speedup 1.0000x reference)
#include <cuda_runtime.h>
#include <math.h>

#define N_NODES 50000
#define N_EDGES 800000
#define ET (N_EDGES + N_NODES)   // edges + self loops
#define D 128
#define BQ 1024
#define H3 384
#define EPSV 1e-5f

#define NEG_INF (__int_as_float(0xff800000))

// ---------------- scratch (device globals; no allocation) ----------------
__device__ float g_h[N_NODES * D];     // W-transformed features
__device__ float g_agg[N_NODES * D];   // attention-aggregated output
__device__ float g_hn[N_NODES * D];    // layer output (norm+relu)
__device__ float g_as[N_NODES];
__device__ float g_ad[N_NODES];
__device__ float g_m[N_NODES];         // segment max
__device__ float g_den[N_NODES];       // segment sum of exp
__device__ float g_e[ET];              // per-edge scratch (e, then exp)
__device__ float g_musum[D];
__device__ float g_varsum[D];
__device__ float g_mu[D];
__device__ float g_istd[D];
__device__ float g_z[BQ * H3];
__device__ float g_z1[BQ * H3];
__device__ float g_z2[BQ * H3];
__device__ float g_lse[BQ];

// ---------------- helpers ----------------
__device__ __forceinline__ void atomicMaxF(float* addr, float v) {
    if (v >= 0.f) atomicMax((int*)addr, __float_as_int(v));
    else          atomicMin((unsigned int*)addr, __float_as_uint(v));
}

// ---------------- init per layer ----------------
__global__ void k_init_layer() {
    int idx = blockIdx.x * blockDim.x + threadIdx.x;
    if (idx < N_NODES * D) g_agg[idx] = 0.f;
    if (idx < N_NODES) { g_m[idx] = NEG_INF; g_den[idx] = 0.f; }
    if (idx < D) { g_musum[idx] = 0.f; g_varsum[idx] = 0.f; }
}

// ---------------- classic 128x128x8 fp32 SGEMM: C[M,N] = A[M,K] * B[N,K]^T (+bias) ----------------
// asel: 0=Aext, 1=g_hn, 2=g_z, 3=g_z2 ; csel: 0=Cext, 1=g_h, 2=g_z1
__global__ __launch_bounds__(256) void k_sgemm_nt(
    const float* __restrict__ Aext, const float* __restrict__ Bm,
    const float* __restrict__ bias, float* __restrict__ Cext,
    int M, int Nn, int K, int asel, int csel)
{
    const float* A = (asel == 0) ? Aext : (asel == 1) ? g_hn : (asel == 2) ? g_z : g_z2;
    float* C = (csel == 0) ? Cext : (csel == 1) ? g_h : g_z1;

    __shared__ float As[8][128];
    __shared__ float Bs[8][128];

    int tid = threadIdx.x;
    int tx = tid & 15, ty = tid >> 4;
    int bm = blockIdx.y * 128, bn = blockIdx.x * 128;

    float acc[8][8];
#pragma unroll
    for (int i = 0; i < 8; i++)
#pragma unroll
        for (int j = 0; j < 8; j++) acc[i][j] = 0.f;

    int lr = tid >> 1;          // 0..127
    int lk = (tid & 1) * 4;     // 0 or 4

    for (int k0 = 0; k0 < K; k0 += 8) {
        float4 a4 = make_float4(0.f, 0.f, 0.f, 0.f);
        int ar = bm + lr;
        if (ar < M) a4 = *(const float4*)(A + (size_t)ar * K + k0 + lk);
        As[lk + 0][lr] = a4.x; As[lk + 1][lr] = a4.y;
        As[lk + 2][lr] = a4.z; As[lk + 3][lr] = a4.w;

        float4 b4 = make_float4(0.f, 0.f, 0.f, 0.f);
        int br = bn + lr;
        if (br < Nn) b4 = *(const float4*)(Bm + (size_t)br * K + k0 + lk);
        Bs[lk + 0][lr] = b4.x; Bs[lk + 1][lr] = b4.y;
        Bs[lk + 2][lr] = b4.z; Bs[lk + 3][lr] = b4.w;
        __syncthreads();

#pragma unroll
        for (int k = 0; k < 8; k++) {
            float4 a0 = *(const float4*)&As[k][ty * 8];
            float4 a1 = *(const float4*)&As[k][ty * 8 + 4];
            float4 b0 = *(const float4*)&Bs[k][tx * 8];
            float4 b1 = *(const float4*)&Bs[k][tx * 8 + 4];
            float a[8] = {a0.x, a0.y, a0.z, a0.w, a1.x, a1.y, a1.z, a1.w};
            float b[8] = {b0.x, b0.y, b0.z, b0.w, b1.x, b1.y, b1.z, b1.w};
#pragma unroll
            for (int i = 0; i < 8; i++)
#pragma unroll
                for (int j = 0; j < 8; j++) acc[i][j] += a[i] * b[j];
        }
        __syncthreads();
    }

#pragma unroll
    for (int i = 0; i < 8; i++) {
        int row = bm + ty * 8 + i;
        if (row >= M) continue;
#pragma unroll
        for (int j = 0; j < 8; j++) {
            int col = bn + tx * 8 + j;
            if (col < Nn) {
                float v = acc[i][j];
                if (bias) v += bias[col];
                C[(size_t)row * Nn + col] = v;
            }
        }
    }
}

// ---------------- attention dot products per node ----------------
__global__ void k_attdot(const float* __restrict__ asrc, const float* __restrict__ adst) {
    int gt = blockIdx.x * blockDim.x + threadIdx.x;
    int node = gt >> 5;
    int lane = gt & 31;
    if (node >= N_NODES) return;
    float4 hv = *(const float4*)(g_h + (size_t)node * D + lane * 4);
    float4 s4 = *(const float4*)(asrc + lane * 4);
    float4 d4 = *(const float4*)(adst + lane * 4);
    float ds = hv.x * s4.x + hv.y * s4.y + hv.z * s4.z + hv.w * s4.w;
    float dd = hv.x * d4.x + hv.y * d4.y + hv.z * d4.z + hv.w * d4.w;
#pragma unroll
    for (int o = 16; o; o >>= 1) {
        ds += __shfl_down_sync(0xffffffff, ds, o);
        dd += __shfl_down_sync(0xffffffff, dd, o);
    }
    if (lane == 0) { g_as[node] = ds; g_ad[node] = dd; }
}

// ---------------- edge pass 1: e + segment max ----------------
__global__ void k_edge_max(const int* __restrict__ ei) {
    int i = blockIdx.x * blockDim.x + threadIdx.x;
    if (i >= ET) return;
    int src, dst;
    if (i < N_EDGES) { src = ei[i]; dst = ei[N_EDGES + i]; }
    else { src = dst = i - N_EDGES; }
    float s = g_as[src] + g_ad[dst];
    float e = (s > 0.f) ? s : 0.2f * s;
    g_e[i] = e;
    atomicMaxF(&g_m[dst], e);
}

// ---------------- edge pass 2: exp + segment sum ----------------
__global__ void k_edge_expsum(const int* __restrict__ ei) {
    int i = blockIdx.x * blockDim.x + threadIdx.x;
    if (i >= ET) return;
    int dst = (i < N_EDGES) ? ei[N_EDGES + i] : (i - N_EDGES);
    float ex = __expf(g_e[i] - g_m[dst]);
    g_e[i] = ex;
    atomicAdd(&g_den[dst], ex);
}

// ---------------- edge pass 3: weighted aggregation (warp per edge) ----------------
__global__ void k_edge_agg(const int* __restrict__ ei) {
    int gt = blockIdx.x * blockDim.x + threadIdx.x;
    int edge = gt >> 5;
    int lane = gt & 31;
    if (edge >= ET) return;
    int src, dst;
    if (edge < N_EDGES) { src = ei[edge]; dst = ei[N_EDGES + edge]; }
    else { src = dst = edge - N_EDGES; }
    float alpha = g_e[edge] / g_den[dst];
    float4 hv = *(const float4*)(g_h + (size_t)src * D + lane * 4);
    float* base = g_agg + (size_t)dst * D + lane * 4;
    atomicAdd(base + 0, hv.x * alpha);
    atomicAdd(base + 1, hv.y * alpha);
    atomicAdd(base + 2, hv.z * alpha);
    atomicAdd(base + 3, hv.w * alpha);
}

// ---------------- GraphNorm column reductions ----------------
#define RPB 64
__global__ void k_colsum() {
    int col = threadIdx.x;
    int r0 = blockIdx.x * RPB;
    int r1 = min(r0 + RPB, N_NODES);
    float s = 0.f;
    for (int r = r0; r < r1; r++) s += g_agg[(size_t)r * D + col];
    atomicAdd(&g_musum[col], s);
}
__global__ void k_fin_mu(const float* __restrict__ bb) {
    int d = threadIdx.x;
    g_mu[d] = g_musum[d] * (1.f / N_NODES) + bb[d];
}
__global__ void k_colvar(const float* __restrict__ bb, const float* __restrict__ ms) {
    int col = threadIdx.x;
    int r0 = blockIdx.x * RPB;
    int r1 = min(r0 + RPB, N_NODES);
    float mu = g_mu[col], msv = ms[col], bv = bb[col];
    float s = 0.f;
    for (int r = r0; r < r1; r++) {
        float t = g_agg[(size_t)r * D + col] + bv - mu * msv;
        s += t * t;
    }
    atomicAdd(&g_varsum[col], s);
}
__global__ void k_fin_istd() {
    int d = threadIdx.x;
    g_istd[d] = rsqrtf(g_varsum[d] * (1.f / N_NODES) + EPSV);
}
__global__ void k_normalize(const float* __restrict__ bb, const float* __restrict__ gw,
                            const float* __restrict__ gb, const float* __restrict__ ms) {
    int idx = blockIdx.x * blockDim.x + threadIdx.x;
    if (idx >= N_NODES * D) return;
    int d = idx & (D - 1);
    float t = g_agg[idx] + bb[d] - g_mu[d] * ms[d];
    float v = t * g_istd[d] * gw[d] + gb[d];
    g_hn[idx] = v > 0.f ? v : 0.f;
}

// ---------------- head ----------------
__global__ void k_gather(const int* __restrict__ x) {
    int idx = blockIdx.x * blockDim.x + threadIdx.x;
    if (idx >= BQ * H3) return;
    int b = idx / H3;
    int rem = idx - b * H3;
    int j = rem >> 7;          // which of 3 slots
    int d = rem & (D - 1);
    int node = x[b * 3 + j];
    g_z[idx] = g_hn[(size_t)node * D + d];
}

__global__ void k_bn_relu(const float* __restrict__ bw, const float* __restrict__ bb) {
    int c = blockIdx.x;        // 0..383
    int t = threadIdx.x;       // 256
    __shared__ float sm[256], ss[256];
    float s = 0.f, s2 = 0.f;
    for (int r = t; r < BQ; r += 256) {
        float v = g_z1[r * H3 + c];
        s += v; s2 += v * v;
    }
    sm[t] = s; ss[t] = s2;
    __syncthreads();
    for (int o = 128; o; o >>= 1) {
        if (t < o) { sm[t] += sm[t + o]; ss[t] += ss[t + o]; }
        __syncthreads();
    }
    float mu = sm[0] * (1.f / BQ);
    float var = ss[0] * (1.f / BQ) - mu * mu;
    float istd = rsqrtf(var + EPSV);
    float w = bw[c], bias = bb[c];
    for (int r = t; r < BQ; r += 256) {
        float v = (g_z1[r * H3 + c] - mu) * istd * w + bias;
        g_z2[r * H3 + c] = v > 0.f ? v : 0.f;
    }
}

// ---------------- log-softmax ----------------
__global__ void k_rowlse(const float* __restrict__ logits) {
    int row = blockIdx.x;
    int t = threadIdx.x;
    const float* p = logits + (size_t)row * N_NODES;
    float m = NEG_INF, s = 0.f;
    for (int c = t; c < N_NODES; c += blockDim.x) {
        float v = p[c];
        if (v > m) { s = s * __expf(m - v) + 1.f; m = v; }
        else s += __expf(v - m);
    }
    __shared__ float sm[256], ss[256];
    sm[t] = m; ss[t] = s;
    __syncthreads();
    for (int o = 128; o; o >>= 1) {
        if (t < o) {
            float m2 = sm[t + o], s2 = ss[t + o];
            float M = fmaxf(sm[t], m2);
            ss[t] = ss[t] * __expf(sm[t] - M) + s2 * __expf(m2 - M);
            sm[t] = M;
        }
        __syncthreads();
    }
    if (t == 0) g_lse[row] = sm[0] + logf(ss[0]);
}

__global__ void k_sub_lse(float* __restrict__ out) {
    int col = blockIdx.x * blockDim.x + threadIdx.x;
    int row = blockIdx.y;
    if (col >= N_NODES) return;
    out[(size_t)row * N_NODES + col] -= g_lse[row];
}

// ---------------- host driver ----------------
static void run_gat_layer(const float* Aext, int asel, const float* W,
                          const float* asrc, const float* adst, const float* bb,
                          const float* gw, const float* gb, const float* gms,
                          const int* ei)
{
    k_init_layer<<<(N_NODES * D + 255) / 256, 256>>>();
    dim3 g1((D + 127) / 128, (N_NODES + 127) / 128);
    k_sgemm_nt<<<g1, 256>>>(Aext, W, nullptr, nullptr, N_NODES, D, D, asel, /*csel=g_h*/1);
    k_attdot<<<(N_NODES * 32 + 255) / 256, 256>>>(asrc, adst);
    k_edge_max<<<(ET + 255) / 256, 256>>>(ei);
    k_edge_expsum<<<(ET + 255) / 256, 256>>>(ei);
    k_edge_agg<<<((size_t)ET * 32 + 255) / 256, 256>>>(ei);
    k_colsum<<<(N_NODES + RPB - 1) / RPB, D>>>();
    k_fin_mu<<<1, D>>>(bb);
    k_colvar<<<(N_NODES + RPB - 1) / RPB, D>>>(bb, gms);
    k_fin_istd<<<1, D>>>();
    k_normalize<<<(N_NODES * D + 255) / 256, 256>>>(bb, gw, gb, gms);
}

extern "C" void kernel_launch(void* const* d_in, const int* in_sizes, int n_in,
                              void* d_out, int out_size)
{
    const int*   x       = (const int*)  d_in[0];
    const int*   ei      = (const int*)  d_in[1];
    const float* emb     = (const float*)d_in[2];
    const float* W1      = (const float*)d_in[3];
    const float* asrc1   = (const float*)d_in[4];
    const float* adst1   = (const float*)d_in[5];
    const float* b1      = (const float*)d_in[6];
    const float* gn1w    = (const float*)d_in[7];
    const float* gn1b    = (const float*)d_in[8];
    const float* gn1ms   = (const float*)d_in[9];
    const float* W2      = (const float*)d_in[10];
    const float* asrc2   = (const float*)d_in[11];
    const float* adst2   = (const float*)d_in[12];
    const float* b2      = (const float*)d_in[13];
    const float* gn2w    = (const float*)d_in[14];
    const float* gn2b    = (const float*)d_in[15];
    const float* gn2ms   = (const float*)d_in[16];
    const float* lin1W   = (const float*)d_in[17];
    const float* lin1b   = (const float*)d_in[18];
    const float* bnw     = (const float*)d_in[19];
    const float* bnb     = (const float*)d_in[20];
    const float* lin2W   = (const float*)d_in[21];
    const float* lin2b   = (const float*)d_in[22];
    float* out = (float*)d_out;

    // GAT layer 1 (input = emb, external) and layer 2 (input = g_hn)
    run_gat_layer(emb, /*asel=*/0, W1, asrc1, adst1, b1, gn1w, gn1b, gn1ms, ei);
    run_gat_layer(nullptr, /*asel=*/1, W2, asrc2, adst2, b2, gn2w, gn2b, gn2ms, ei);

    // head: gather -> lin1 -> BN+relu -> lin2 (logits into d_out) -> log-softmax
    k_gather<<<(BQ * H3 + 255) / 256, 256>>>(x);
    dim3 gz1((H3 + 127) / 128, (BQ + 127) / 128);
    k_sgemm_nt<<<gz1, 256>>>(nullptr, lin1W, lin1b, nullptr, BQ, H3, H3, /*asel=g_z*/2, /*csel=g_z1*/2);
    k_bn_relu<<<H3, 256>>>(bnw, bnb);
    dim3 gz2((N_NODES + 127) / 128, (BQ + 127) / 128);
    k_sgemm_nt<<<gz2, 256>>>(nullptr, lin2W, lin2b, out, BQ, N_NODES, H3, /*asel=g_z2*/3, /*csel=out*/0);
    k_rowlse<<<BQ, 256>>>(out);
    dim3 gs((N_NODES + 255) / 256, BQ);
    k_sub_lse<<<gs, 256>>>(out);
}

// round 3
// speedup vs baseline: 1.8109x; 1.8109x over previous
#include <cuda_runtime.h>
#include <math.h>
#include <stdint.h>

#define N_NODES 50000
#define N_EDGES 800000
#define ET (N_EDGES + N_NODES)   // edges + self loops
#define D 128
#define BQ 1024
#define H3 384
#define EPSV 1e-5f

#define NEG_INF (__int_as_float(0xff800000))

// ---------------- scratch (device globals; no allocation) ----------------
__device__ float g_h[N_NODES * D];     // W-transformed features
__device__ float g_agg[N_NODES * D];   // attention-aggregated output
__device__ float g_hn[N_NODES * D];    // layer output (norm+relu)
__device__ float g_as[N_NODES];
__device__ float g_ad[N_NODES];
__device__ float g_e[ET];              // per-edge scratch (e, then exp), CSR order
__device__ float g_musum[D];
__device__ float g_varsum[D];
__device__ float g_mu[D];
__device__ float g_istd[D];
__device__ float g_z[BQ * H3];
__device__ float g_z1[BQ * H3];
__device__ float g_z2[BQ * H3];
__device__ float g_lse[BQ];
// CSR
__device__ int g_deg[N_NODES];
__device__ int g_off[N_NODES + 1];
__device__ int g_cur[N_NODES];
__device__ int g_srcl[ET];

// ================= CSR build =================
__global__ void k_zero_deg() {
    int i = blockIdx.x * blockDim.x + threadIdx.x;
    if (i < N_NODES) g_deg[i] = 0;
}
__global__ void k_count(const int* __restrict__ ei) {
    int i = blockIdx.x * blockDim.x + threadIdx.x;
    if (i >= ET) return;
    int dst = (i < N_EDGES) ? ei[N_EDGES + i] : (i - N_EDGES);
    atomicAdd(&g_deg[dst], 1);
}
__global__ void k_scan() {       // exclusive scan of g_deg -> g_off
    __shared__ int swarp[32];
    __shared__ int carry;
    int tid = threadIdx.x;
    int lane = tid & 31, wid = tid >> 5;
    if (tid == 0) carry = 0;
    __syncthreads();
    for (int base = 0; base < N_NODES; base += 1024) {
        int v = (base + tid < N_NODES) ? g_deg[base + tid] : 0;
        int x = v;
#pragma unroll
        for (int o = 1; o < 32; o <<= 1) {
            int t = __shfl_up_sync(0xffffffff, x, o);
            if (lane >= o) x += t;
        }
        if (lane == 31) swarp[wid] = x;
        __syncthreads();
        if (wid == 0) {
            int y = swarp[lane];
#pragma unroll
            for (int o = 1; o < 32; o <<= 1) {
                int t = __shfl_up_sync(0xffffffff, y, o);
                if (lane >= o) y += t;
            }
            swarp[lane] = y;
        }
        __syncthreads();
        int prefix = (wid > 0) ? swarp[wid - 1] : 0;
        int incl = x + prefix;
        if (base + tid < N_NODES) g_off[base + tid] = carry + incl - v;
        __syncthreads();
        if (tid == 0) carry += swarp[31];
        __syncthreads();
    }
    if (tid == 0) g_off[N_NODES] = ET;
}
__global__ void k_copyoff() {
    int i = blockIdx.x * blockDim.x + threadIdx.x;
    if (i < N_NODES) g_cur[i] = g_off[i];
}
__global__ void k_fill(const int* __restrict__ ei) {
    int i = blockIdx.x * blockDim.x + threadIdx.x;
    if (i >= ET) return;
    int src, dst;
    if (i < N_EDGES) { src = ei[i]; dst = ei[N_EDGES + i]; }
    else { src = dst = i - N_EDGES; }
    int pos = atomicAdd(&g_cur[dst], 1);
    g_srcl[pos] = src;
}

// ================= fp32 SGEMM (feature / lin1 GEMMs) =================
// C[M,N] = A[M,K] * B[N,K]^T (+bias)
// asel: 0=Aext, 1=g_hn, 2=g_z ; csel: 1=g_h, 2=g_z1
__global__ __launch_bounds__(256) void k_sgemm_nt(
    const float* __restrict__ Aext, const float* __restrict__ Bm,
    const float* __restrict__ bias,
    int M, int Nn, int K, int asel, int csel)
{
    const float* A = (asel == 0) ? Aext : (asel == 1) ? g_hn : g_z;
    float* C = (csel == 1) ? g_h : g_z1;

    __shared__ float As[8][128];
    __shared__ float Bs[8][128];

    int tid = threadIdx.x;
    int tx = tid & 15, ty = tid >> 4;
    int bm = blockIdx.y * 128, bn = blockIdx.x * 128;

    float acc[8][8];
#pragma unroll
    for (int i = 0; i < 8; i++)
#pragma unroll
        for (int j = 0; j < 8; j++) acc[i][j] = 0.f;

    int lr = tid >> 1;
    int lk = (tid & 1) * 4;

    for (int k0 = 0; k0 < K; k0 += 8) {
        float4 a4 = make_float4(0.f, 0.f, 0.f, 0.f);
        int ar = bm + lr;
        if (ar < M) a4 = *(const float4*)(A + (size_t)ar * K + k0 + lk);
        As[lk + 0][lr] = a4.x; As[lk + 1][lr] = a4.y;
        As[lk + 2][lr] = a4.z; As[lk + 3][lr] = a4.w;

        float4 b4 = make_float4(0.f, 0.f, 0.f, 0.f);
        int br = bn + lr;
        if (br < Nn) b4 = *(const float4*)(Bm + (size_t)br * K + k0 + lk);
        Bs[lk + 0][lr] = b4.x; Bs[lk + 1][lr] = b4.y;
        Bs[lk + 2][lr] = b4.z; Bs[lk + 3][lr] = b4.w;
        __syncthreads();

#pragma unroll
        for (int k = 0; k < 8; k++) {
            float4 a0 = *(const float4*)&As[k][ty * 8];
            float4 a1 = *(const float4*)&As[k][ty * 8 + 4];
            float4 b0 = *(const float4*)&Bs[k][tx * 8];
            float4 b1 = *(const float4*)&Bs[k][tx * 8 + 4];
            float a[8] = {a0.x, a0.y, a0.z, a0.w, a1.x, a1.y, a1.z, a1.w};
            float b[8] = {b0.x, b0.y, b0.z, b0.w, b1.x, b1.y, b1.z, b1.w};
#pragma unroll
            for (int i = 0; i < 8; i++)
#pragma unroll
                for (int j = 0; j < 8; j++) acc[i][j] += a[i] * b[j];
        }
        __syncthreads();
    }

#pragma unroll
    for (int i = 0; i < 8; i++) {
        int row = bm + ty * 8 + i;
        if (row >= M) continue;
#pragma unroll
        for (int j = 0; j < 8; j++) {
            int col = bn + tx * 8 + j;
            if (col < Nn) {
                float v = acc[i][j];
                if (bias) v += bias[col];
                C[(size_t)row * Nn + col] = v;
            }
        }
    }
}

// ================= tf32 tensor-core GEMM for lin2 =================
// out[BQ, N_NODES] = g_z2[BQ, H3] @ W[N_NODES, H3]^T + bias
__device__ __forceinline__ uint32_t f2tf32(float f) {
    uint32_t u;
    asm("cvt.rna.tf32.f32 %0, %1;" : "=r"(u) : "f"(f));
    return u;
}
__device__ __forceinline__ void mma_tf32(float c[4], uint32_t a0, uint32_t a1,
                                         uint32_t a2, uint32_t a3,
                                         uint32_t b0, uint32_t b1) {
    asm volatile(
        "mma.sync.aligned.m16n8k8.row.col.f32.tf32.tf32.f32 "
        "{%0,%1,%2,%3}, {%4,%5,%6,%7}, {%8,%9}, {%0,%1,%2,%3};"
        : "+f"(c[0]), "+f"(c[1]), "+f"(c[2]), "+f"(c[3])
        : "r"(a0), "r"(a1), "r"(a2), "r"(a3), "r"(b0), "r"(b1));
}

__global__ __launch_bounds__(256) void k_mma_lin2(
    const float* __restrict__ Bm, const float* __restrict__ bias,
    float* __restrict__ out)
{
    const int K = H3, Nn = N_NODES;
    __shared__ uint32_t As[32][136];
    __shared__ uint32_t Bs[32][136];

    int tid = threadIdx.x;
    int warp = tid >> 5, lane = tid & 31;
    int wm = (warp & 1) * 64;   // 2 warps along M
    int wn = (warp >> 1) * 32;  // 4 warps along N
    int bm = blockIdx.y * 128;
    int bn = blockIdx.x * 128;

    float c[4][4][4];
#pragma unroll
    for (int mt = 0; mt < 4; mt++)
#pragma unroll
        for (int nt = 0; nt < 4; nt++)
#pragma unroll
            for (int r = 0; r < 4; r++) c[mt][nt][r] = 0.f;

    int gr = lane >> 2, gc = lane & 3;

    for (int k0 = 0; k0 < K; k0 += 32) {
        // stage A tile 128x32 (row-major source, k-major smem)
#pragma unroll
        for (int l = 0; l < 4; l++) {
            int linear = tid + l * 256;
            int row = linear & 127, kq = linear >> 7;     // kq 0..7
            float4 v = *(const float4*)(g_z2 + (size_t)(bm + row) * K + k0 + kq * 4);
            As[kq * 4 + 0][row] = f2tf32(v.x);
            As[kq * 4 + 1][row] = f2tf32(v.y);
            As[kq * 4 + 2][row] = f2tf32(v.z);
            As[kq * 4 + 3][row] = f2tf32(v.w);
        }
        // stage B tile 128x32
#pragma unroll
        for (int l = 0; l < 4; l++) {
            int linear = tid + l * 256;
            int row = linear & 127, kq = linear >> 7;
            int grow = bn + row;
            float4 v = make_float4(0.f, 0.f, 0.f, 0.f);
            if (grow < Nn) v = *(const float4*)(Bm + (size_t)grow * K + k0 + kq * 4);
            Bs[kq * 4 + 0][row] = f2tf32(v.x);
            Bs[kq * 4 + 1][row] = f2tf32(v.y);
            Bs[kq * 4 + 2][row] = f2tf32(v.z);
            Bs[kq * 4 + 3][row] = f2tf32(v.w);
        }
        __syncthreads();

#pragma unroll
        for (int ks = 0; ks < 4; ks++) {
            int kb = ks * 8;
            uint32_t a[4][4];
#pragma unroll
            for (int mt = 0; mt < 4; mt++) {
                int mrow = wm + mt * 16 + gr;
                a[mt][0] = As[kb + gc][mrow];
                a[mt][1] = As[kb + gc][mrow + 8];
                a[mt][2] = As[kb + gc + 4][mrow];
                a[mt][3] = As[kb + gc + 4][mrow + 8];
            }
            uint32_t b[4][2];
#pragma unroll
            for (int nt = 0; nt < 4; nt++) {
                int ncol = wn + nt * 8 + gr;
                b[nt][0] = Bs[kb + gc][ncol];
                b[nt][1] = Bs[kb + gc + 4][ncol];
            }
#pragma unroll
            for (int mt = 0; mt < 4; mt++)
#pragma unroll
                for (int nt = 0; nt < 4; nt++)
                    mma_tf32(c[mt][nt], a[mt][0], a[mt][1], a[mt][2], a[mt][3],
                             b[nt][0], b[nt][1]);
        }
        __syncthreads();
    }

    // epilogue
    int crow = lane >> 2, ccol = (lane & 3) * 2;
#pragma unroll
    for (int mt = 0; mt < 4; mt++) {
#pragma unroll
        for (int nt = 0; nt < 4; nt++) {
            int row0 = bm + wm + mt * 16 + crow;
            int col0 = bn + wn + nt * 8 + ccol;
            if (col0 < Nn) {
                float bv0 = bias[col0];
                out[(size_t)row0 * Nn + col0] = c[mt][nt][0] + bv0;
                out[(size_t)(row0 + 8) * Nn + col0] = c[mt][nt][2] + bv0;
            }
            if (col0 + 1 < Nn) {
                float bv1 = bias[col0 + 1];
                out[(size_t)row0 * Nn + col0 + 1] = c[mt][nt][1] + bv1;
                out[(size_t)(row0 + 8) * Nn + col0 + 1] = c[mt][nt][3] + bv1;
            }
        }
    }
}

// ================= per-node attention kernels =================
__global__ void k_attdot(const float* __restrict__ asrc, const float* __restrict__ adst) {
    int gt = blockIdx.x * blockDim.x + threadIdx.x;
    int node = gt >> 5;
    int lane = gt & 31;
    if (node >= N_NODES) return;
    float4 hv = *(const float4*)(g_h + (size_t)node * D + lane * 4);
    float4 s4 = *(const float4*)(asrc + lane * 4);
    float4 d4 = *(const float4*)(adst + lane * 4);
    float ds = hv.x * s4.x + hv.y * s4.y + hv.z * s4.z + hv.w * s4.w;
    float dd = hv.x * d4.x + hv.y * d4.y + hv.z * d4.z + hv.w * d4.w;
#pragma unroll
    for (int o = 16; o; o >>= 1) {
        ds += __shfl_down_sync(0xffffffff, ds, o);
        dd += __shfl_down_sync(0xffffffff, dd, o);
    }
    if (lane == 0) { g_as[node] = ds; g_ad[node] = dd; }
}

// fused segment softmax + weighted aggregation, warp per node, no atomics
__global__ void k_node_attagg() {
    int gt = blockIdx.x * blockDim.x + threadIdx.x;
    int node = gt >> 5, lane = gt & 31;
    if (node >= N_NODES) return;
    int beg = g_off[node], end = g_off[node + 1];
    float ad = g_ad[node];

    float m = NEG_INF;
    for (int i = beg + lane; i < end; i += 32) {
        float s = g_as[g_srcl[i]] + ad;
        float e = (s > 0.f) ? s : 0.2f * s;
        g_e[i] = e;
        m = fmaxf(m, e);
    }
#pragma unroll
    for (int o = 16; o; o >>= 1) m = fmaxf(m, __shfl_xor_sync(0xffffffff, m, o));

    __syncwarp();
    float den = 0.f;
    for (int i = beg + lane; i < end; i += 32) {
        float ex = __expf(g_e[i] - m);
        g_e[i] = ex;
        den += ex;
    }
#pragma unroll
    for (int o = 16; o; o >>= 1) den += __shfl_xor_sync(0xffffffff, den, o);
    float inv = 1.f / den;
    __syncwarp();

    float4 acc = make_float4(0.f, 0.f, 0.f, 0.f);
    for (int i = beg; i < end; i++) {
        float w = g_e[i] * inv;
        int s = g_srcl[i];
        float4 hv = *(const float4*)(g_h + (size_t)s * D + lane * 4);
        acc.x += w * hv.x; acc.y += w * hv.y;
        acc.z += w * hv.z; acc.w += w * hv.w;
    }
    *(float4*)(g_agg + (size_t)node * D + lane * 4) = acc;
}

// ================= GraphNorm =================
#define RPB 64
__global__ void k_zero_stats() {
    int d = threadIdx.x;
    g_musum[d] = 0.f; g_varsum[d] = 0.f;
}
__global__ void k_colsum() {
    int col = threadIdx.x;
    int r0 = blockIdx.x * RPB;
    int r1 = min(r0 + RPB, N_NODES);
    float s = 0.f;
    for (int r = r0; r < r1; r++) s += g_agg[(size_t)r * D + col];
    atomicAdd(&g_musum[col], s);
}
__global__ void k_fin_mu(const float* __restrict__ bb) {
    int d = threadIdx.x;
    g_mu[d] = g_musum[d] * (1.f / N_NODES) + bb[d];
}
__global__ void k_colvar(const float* __restrict__ bb, const float* __restrict__ ms) {
    int col = threadIdx.x;
    int r0 = blockIdx.x * RPB;
    int r1 = min(r0 + RPB, N_NODES);
    float mu = g_mu[col], msv = ms[col], bv = bb[col];
    float s = 0.f;
    for (int r = r0; r < r1; r++) {
        float t = g_agg[(size_t)r * D + col] + bv - mu * msv;
        s += t * t;
    }
    atomicAdd(&g_varsum[col], s);
}
__global__ void k_fin_istd() {
    int d = threadIdx.x;
    g_istd[d] = rsqrtf(g_varsum[d] * (1.f / N_NODES) + EPSV);
}
__global__ void k_normalize(const float* __restrict__ bb, const float* __restrict__ gw,
                            const float* __restrict__ gb, const float* __restrict__ ms) {
    int idx = blockIdx.x * blockDim.x + threadIdx.x;
    if (idx >= N_NODES * D) return;
    int d = idx & (D - 1);
    float t = g_agg[idx] + bb[d] - g_mu[d] * ms[d];
    float v = t * g_istd[d] * gw[d] + gb[d];
    g_hn[idx] = v > 0.f ? v : 0.f;
}

// ================= head =================
__global__ void k_gather(const int* __restrict__ x) {
    int idx = blockIdx.x * blockDim.x + threadIdx.x;
    if (idx >= BQ * H3) return;
    int b = idx / H3;
    int rem = idx - b * H3;
    int j = rem >> 7;
    int d = rem & (D - 1);
    int node = x[b * 3 + j];
    g_z[idx] = g_hn[(size_t)node * D + d];
}

__global__ void k_bn_relu(const float* __restrict__ bw, const float* __restrict__ bb) {
    int c = blockIdx.x;
    int t = threadIdx.x;
    __shared__ float sm[256], ss[256];
    float s = 0.f, s2 = 0.f;
    for (int r = t; r < BQ; r += 256) {
        float v = g_z1[r * H3 + c];
        s += v; s2 += v * v;
    }
    sm[t] = s; ss[t] = s2;
    __syncthreads();
    for (int o = 128; o; o >>= 1) {
        if (t < o) { sm[t] += sm[t + o]; ss[t] += ss[t + o]; }
        __syncthreads();
    }
    float mu = sm[0] * (1.f / BQ);
    float var = ss[0] * (1.f / BQ) - mu * mu;
    float istd = rsqrtf(var + EPSV);
    float w = bw[c], bias = bb[c];
    for (int r = t; r < BQ; r += 256) {
        float v = (g_z1[r * H3 + c] - mu) * istd * w + bias;
        g_z2[r * H3 + c] = v > 0.f ? v : 0.f;
    }
}

// ================= log-softmax =================
__global__ void k_rowlse(const float* __restrict__ logits) {
    int row = blockIdx.x;
    int t = threadIdx.x;
    const float* p = logits + (size_t)row * N_NODES;
    float m = NEG_INF, s = 0.f;
    for (int c = t; c < N_NODES; c += blockDim.x) {
        float v = p[c];
        if (v > m) { s = s * __expf(m - v) + 1.f; m = v; }
        else s += __expf(v - m);
    }
    __shared__ float sm[256], ss[256];
    sm[t] = m; ss[t] = s;
    __syncthreads();
    for (int o = 128; o; o >>= 1) {
        if (t < o) {
            float m2 = sm[t + o], s2 = ss[t + o];
            float M = fmaxf(sm[t], m2);
            ss[t] = ss[t] * __expf(sm[t] - M) + s2 * __expf(m2 - M);
            sm[t] = M;
        }
        __syncthreads();
    }
    if (t == 0) g_lse[row] = sm[0] + logf(ss[0]);
}

__global__ void k_sub_lse(float* __restrict__ out) {
    int col = blockIdx.x * blockDim.x + threadIdx.x;
    int row = blockIdx.y;
    if (col >= N_NODES) return;
    out[(size_t)row * N_NODES + col] -= g_lse[row];
}

// ================= host driver =================
static void run_gat_layer(const float* Aext, int asel, const float* W,
                          const float* asrc, const float* adst, const float* bb,
                          const float* gw, const float* gb, const float* gms)
{
    k_zero_stats<<<1, D>>>();
    dim3 g1(1, (N_NODES + 127) / 128);
    k_sgemm_nt<<<g1, 256>>>(Aext, W, nullptr, N_NODES, D, D, asel, /*csel=g_h*/1);
    k_attdot<<<(N_NODES * 32 + 255) / 256, 256>>>(asrc, adst);
    k_node_attagg<<<(N_NODES * 32 + 255) / 256, 256>>>();
    k_colsum<<<(N_NODES + RPB - 1) / RPB, D>>>();
    k_fin_mu<<<1, D>>>(bb);
    k_colvar<<<(N_NODES + RPB - 1) / RPB, D>>>(bb, gms);
    k_fin_istd<<<1, D>>>();
    k_normalize<<<(N_NODES * D + 255) / 256, 256>>>(bb, gw, gb, gms);
}

extern "C" void kernel_launch(void* const* d_in, const int* in_sizes, int n_in,
                              void* d_out, int out_size)
{
    const int*   x       = (const int*)  d_in[0];
    const int*   ei      = (const int*)  d_in[1];
    const float* emb     = (const float*)d_in[2];
    const float* W1      = (const float*)d_in[3];
    const float* asrc1   = (const float*)d_in[4];
    const float* adst1   = (const float*)d_in[5];
    const float* b1      = (const float*)d_in[6];
    const float* gn1w    = (const float*)d_in[7];
    const float* gn1b    = (const float*)d_in[8];
    const float* gn1ms   = (const float*)d_in[9];
    const float* W2      = (const float*)d_in[10];
    const float* asrc2   = (const float*)d_in[11];
    const float* adst2   = (const float*)d_in[12];
    const float* b2      = (const float*)d_in[13];
    const float* gn2w    = (const float*)d_in[14];
    const float* gn2b    = (const float*)d_in[15];
    const float* gn2ms   = (const float*)d_in[16];
    const float* lin1W   = (const float*)d_in[17];
    const float* lin1b   = (const float*)d_in[18];
    const float* bnw     = (const float*)d_in[19];
    const float* bnb     = (const float*)d_in[20];
    const float* lin2W   = (const float*)d_in[21];
    const float* lin2b   = (const float*)d_in[22];
    float* out = (float*)d_out;

    // --- CSR build (reused by both layers) ---
    k_zero_deg<<<(N_NODES + 255) / 256, 256>>>();
    k_count<<<(ET + 255) / 256, 256>>>(ei);
    k_scan<<<1, 1024>>>();
    k_copyoff<<<(N_NODES + 255) / 256, 256>>>();
    k_fill<<<(ET + 255) / 256, 256>>>(ei);

    // --- GAT layers ---
    run_gat_layer(emb, /*asel=*/0, W1, asrc1, adst1, b1, gn1w, gn1b, gn1ms);
    run_gat_layer(nullptr, /*asel=*/1, W2, asrc2, adst2, b2, gn2w, gn2b, gn2ms);

    // --- head ---
    k_gather<<<(BQ * H3 + 255) / 256, 256>>>(x);
    dim3 gz1((H3 + 127) / 128, (BQ + 127) / 128);
    k_sgemm_nt<<<gz1, 256>>>(nullptr, lin1W, lin1b, BQ, H3, H3, /*asel=g_z*/2, /*csel=g_z1*/2);
    k_bn_relu<<<H3, 256>>>(bnw, bnb);
    dim3 gz2((N_NODES + 127) / 128, (BQ + 127) / 128);
    k_mma_lin2<<<gz2, 256>>>(lin2W, lin2b, out);
    k_rowlse<<<BQ, 256>>>(out);
    dim3 gs((N_NODES + 255) / 256, BQ);
    k_sub_lse<<<gs, 256>>>(out);
}

// round 4
// speedup vs baseline: 2.5681x; 1.4181x over previous
#include <cuda_runtime.h>
#include <math.h>
#include <stdint.h>

#define N_NODES 50000
#define N_EDGES 800000
#define ET (N_EDGES + N_NODES)   // edges + self loops
#define D 128
#define BQ 1024
#define H3 384
#define EPSV 1e-5f
#define NT_TILES 391             // ceil(50000/128)

#define NEG_INF (__int_as_float(0xff800000))

// ---------------- scratch (device globals; no allocation) ----------------
__device__ float g_h[N_NODES * D];
__device__ float g_agg[N_NODES * D];
__device__ float g_hn[N_NODES * D];
__device__ float g_as[N_NODES];
__device__ float g_ad[N_NODES];
__device__ float g_e[ET];
__device__ float g_musum[D];
__device__ float g_varsum[D];
__device__ float g_mu[D];
__device__ float g_istd[D];
__device__ float g_z[BQ * H3];
__device__ float g_z1[BQ * H3];
__device__ float g_z2[BQ * H3];
__device__ float g_lse[BQ];
__device__ float g_pmax[(size_t)BQ * NT_TILES];
__device__ float g_psum[(size_t)BQ * NT_TILES];
// CSR
__device__ int g_deg[N_NODES];
__device__ int g_off[N_NODES + 1];
__device__ int g_cur[N_NODES];
__device__ int g_srcl[ET];

// ================= CSR build =================
__global__ void k_zero_deg() {
    int i = blockIdx.x * blockDim.x + threadIdx.x;
    if (i < N_NODES) g_deg[i] = 0;
}
__global__ void k_count(const int* __restrict__ ei) {
    int i = blockIdx.x * blockDim.x + threadIdx.x;
    if (i >= ET) return;
    int dst = (i < N_EDGES) ? ei[N_EDGES + i] : (i - N_EDGES);
    atomicAdd(&g_deg[dst], 1);
}
__global__ void k_scan() {
    __shared__ int swarp[32];
    __shared__ int carry;
    int tid = threadIdx.x;
    int lane = tid & 31, wid = tid >> 5;
    if (tid == 0) carry = 0;
    __syncthreads();
    for (int base = 0; base < N_NODES; base += 1024) {
        int v = (base + tid < N_NODES) ? g_deg[base + tid] : 0;
        int x = v;
#pragma unroll
        for (int o = 1; o < 32; o <<= 1) {
            int t = __shfl_up_sync(0xffffffff, x, o);
            if (lane >= o) x += t;
        }
        if (lane == 31) swarp[wid] = x;
        __syncthreads();
        if (wid == 0) {
            int y = swarp[lane];
#pragma unroll
            for (int o = 1; o < 32; o <<= 1) {
                int t = __shfl_up_sync(0xffffffff, y, o);
                if (lane >= o) y += t;
            }
            swarp[lane] = y;
        }
        __syncthreads();
        int prefix = (wid > 0) ? swarp[wid - 1] : 0;
        int incl = x + prefix;
        if (base + tid < N_NODES) g_off[base + tid] = carry + incl - v;
        __syncthreads();
        if (tid == 0) carry += swarp[31];
        __syncthreads();
    }
    if (tid == 0) g_off[N_NODES] = ET;
}
__global__ void k_copyoff() {
    int i = blockIdx.x * blockDim.x + threadIdx.x;
    if (i < N_NODES) g_cur[i] = g_off[i];
}
__global__ void k_fill(const int* __restrict__ ei) {
    int i = blockIdx.x * blockDim.x + threadIdx.x;
    if (i >= ET) return;
    int src, dst;
    if (i < N_EDGES) { src = ei[i]; dst = ei[N_EDGES + i]; }
    else { src = dst = i - N_EDGES; }
    int pos = atomicAdd(&g_cur[dst], 1);
    g_srcl[pos] = src;
}

// ================= fp32 SGEMM (feature / lin1 GEMMs) =================
__global__ __launch_bounds__(256) void k_sgemm_nt(
    const float* __restrict__ Aext, const float* __restrict__ Bm,
    const float* __restrict__ bias,
    int M, int Nn, int K, int asel, int csel)
{
    const float* A = (asel == 0) ? Aext : (asel == 1) ? g_hn : g_z;
    float* C = (csel == 1) ? g_h : g_z1;

    __shared__ float As[8][128];
    __shared__ float Bs[8][128];

    int tid = threadIdx.x;
    int tx = tid & 15, ty = tid >> 4;
    int bm = blockIdx.y * 128, bn = blockIdx.x * 128;

    float acc[8][8];
#pragma unroll
    for (int i = 0; i < 8; i++)
#pragma unroll
        for (int j = 0; j < 8; j++) acc[i][j] = 0.f;

    int lr = tid >> 1;
    int lk = (tid & 1) * 4;

    for (int k0 = 0; k0 < K; k0 += 8) {
        float4 a4 = make_float4(0.f, 0.f, 0.f, 0.f);
        int ar = bm + lr;
        if (ar < M) a4 = *(const float4*)(A + (size_t)ar * K + k0 + lk);
        As[lk + 0][lr] = a4.x; As[lk + 1][lr] = a4.y;
        As[lk + 2][lr] = a4.z; As[lk + 3][lr] = a4.w;

        float4 b4 = make_float4(0.f, 0.f, 0.f, 0.f);
        int br = bn + lr;
        if (br < Nn) b4 = *(const float4*)(Bm + (size_t)br * K + k0 + lk);
        Bs[lk + 0][lr] = b4.x; Bs[lk + 1][lr] = b4.y;
        Bs[lk + 2][lr] = b4.z; Bs[lk + 3][lr] = b4.w;
        __syncthreads();

#pragma unroll
        for (int k = 0; k < 8; k++) {
            float4 a0 = *(const float4*)&As[k][ty * 8];
            float4 a1 = *(const float4*)&As[k][ty * 8 + 4];
            float4 b0 = *(const float4*)&Bs[k][tx * 8];
            float4 b1 = *(const float4*)&Bs[k][tx * 8 + 4];
            float a[8] = {a0.x, a0.y, a0.z, a0.w, a1.x, a1.y, a1.z, a1.w};
            float b[8] = {b0.x, b0.y, b0.z, b0.w, b1.x, b1.y, b1.z, b1.w};
#pragma unroll
            for (int i = 0; i < 8; i++)
#pragma unroll
                for (int j = 0; j < 8; j++) acc[i][j] += a[i] * b[j];
        }
        __syncthreads();
    }

#pragma unroll
    for (int i = 0; i < 8; i++) {
        int row = bm + ty * 8 + i;
        if (row >= M) continue;
#pragma unroll
        for (int j = 0; j < 8; j++) {
            int col = bn + tx * 8 + j;
            if (col < Nn) {
                float v = acc[i][j];
                if (bias) v += bias[col];
                C[(size_t)row * Nn + col] = v;
            }
        }
    }
}

// ================= tf32 tensor-core GEMM for lin2 (+ fused LSE partials) ===
__device__ __forceinline__ void mma_tf32(float c[4], uint32_t a0, uint32_t a1,
                                         uint32_t a2, uint32_t a3,
                                         uint32_t b0, uint32_t b1) {
    asm volatile(
        "mma.sync.aligned.m16n8k8.row.col.f32.tf32.tf32.f32 "
        "{%0,%1,%2,%3}, {%4,%5,%6,%7}, {%8,%9}, {%0,%1,%2,%3};"
        : "+f"(c[0]), "+f"(c[1]), "+f"(c[2]), "+f"(c[3])
        : "r"(a0), "r"(a1), "r"(a2), "r"(a3), "r"(b0), "r"(b1));
}
__device__ __forceinline__ void cp_async16(uint32_t saddr, const void* gptr, int srcBytes) {
    asm volatile("cp.async.cg.shared.global [%0], [%1], 16, %2;\n"
                 :: "r"(saddr), "l"(gptr), "r"(srcBytes));
}
__device__ __forceinline__ void cp_commit() {
    asm volatile("cp.async.commit_group;\n");
}
template <int NW>
__device__ __forceinline__ void cp_wait() {
    asm volatile("cp.async.wait_group %0;\n" :: "n"(NW));
}

// tiles: BM=128, BN=128, BK=32; 2-stage cp.async; pad rows to 36 floats
#define MMA_PAD 36
#define MMA_STAGE_F (128 * MMA_PAD)            // floats per operand per stage
#define MMA_SMEM_F (4 * MMA_STAGE_F)           // A0,A1,B0,B1
__global__ __launch_bounds__(256) void k_mma_lin2(
    const float* __restrict__ Bm, const float* __restrict__ bias,
    float* __restrict__ out)
{
    extern __shared__ float smem[];
    const int K = H3, Nn = N_NODES;
    float* Abuf = smem;                    // [2][128][36]
    float* Bbuf = smem + 2 * MMA_STAGE_F;  // [2][128][36]

    int tid = threadIdx.x;
    int warp = tid >> 5, lane = tid & 31;
    int wm = (warp & 1) * 64;
    int wnw = warp >> 1;          // 0..3
    int wn = wnw * 32;
    int bm = blockIdx.y * 128;
    int bn = blockIdx.x * 128;

    float c[4][4][4];
#pragma unroll
    for (int mt = 0; mt < 4; mt++)
#pragma unroll
        for (int nt = 0; nt < 4; nt++)
#pragma unroll
            for (int r = 0; r < 4; r++) c[mt][nt][r] = 0.f;

    int gr = lane >> 2, gc = lane & 3;

    // async tile loader: per thread 4 chunks of A + 4 chunks of B
    auto load_tile = [&](int it, int stage) {
        int k0 = it * 32;
        float* Ad = Abuf + stage * MMA_STAGE_F;
        float* Bd = Bbuf + stage * MMA_STAGE_F;
#pragma unroll
        for (int l = 0; l < 4; l++) {
            int linear = tid + l * 256;         // 0..1023
            int row = linear >> 3;
            int kc = (linear & 7) * 4;
            uint32_t sa = (uint32_t)__cvta_generic_to_shared(Ad + row * MMA_PAD + kc);
            cp_async16(sa, g_z2 + (size_t)(bm + row) * K + k0 + kc, 16);
            int grow = bn + row;
            int ok = (grow < Nn);
            uint32_t sb = (uint32_t)__cvta_generic_to_shared(Bd + row * MMA_PAD + kc);
            cp_async16(sb, Bm + (size_t)(ok ? grow : 0) * K + k0 + kc, ok ? 16 : 0);
        }
        cp_commit();
    };

    const int NIT = K / 32;   // 12
    load_tile(0, 0);
    for (int it = 0; it < NIT; it++) {
        int cur = it & 1;
        if (it + 1 < NIT) { load_tile(it + 1, cur ^ 1); cp_wait<1>(); }
        else cp_wait<0>();
        __syncthreads();

        const float* Ac = Abuf + cur * MMA_STAGE_F;
        const float* Bc = Bbuf + cur * MMA_STAGE_F;
#pragma unroll
        for (int ks = 0; ks < 4; ks++) {
            int kb = ks * 8;
            uint32_t a[4][4];
#pragma unroll
            for (int mt = 0; mt < 4; mt++) {
                int mrow = wm + mt * 16 + gr;
                a[mt][0] = __float_as_uint(Ac[mrow * MMA_PAD + kb + gc]);
                a[mt][1] = __float_as_uint(Ac[(mrow + 8) * MMA_PAD + kb + gc]);
                a[mt][2] = __float_as_uint(Ac[mrow * MMA_PAD + kb + gc + 4]);
                a[mt][3] = __float_as_uint(Ac[(mrow + 8) * MMA_PAD + kb + gc + 4]);
            }
            uint32_t b[4][2];
#pragma unroll
            for (int nt = 0; nt < 4; nt++) {
                int ncol = wn + nt * 8 + gr;
                b[nt][0] = __float_as_uint(Bc[ncol * MMA_PAD + kb + gc]);
                b[nt][1] = __float_as_uint(Bc[ncol * MMA_PAD + kb + gc + 4]);
            }
#pragma unroll
            for (int mt = 0; mt < 4; mt++)
#pragma unroll
                for (int nt = 0; nt < 4; nt++)
                    mma_tf32(c[mt][nt], a[mt][0], a[mt][1], a[mt][2], a[mt][3],
                             b[nt][0], b[nt][1]);
        }
        __syncthreads();
    }

    // ---- epilogue: bias add + store + per-row (max, sumexp) partials ----
    float* sm_pm  = smem;              // [128][4]
    float* sm_max = smem + 512;        // [128]
    float* sm_ps  = smem + 512 + 128;  // [128][4]

    int crow = lane >> 2, ccol = (lane & 3) * 2;
    float bv[4][2];
    bool ok[4][2];
#pragma unroll
    for (int nt = 0; nt < 4; nt++)
#pragma unroll
        for (int j = 0; j < 2; j++) {
            int col = bn + wn + nt * 8 + ccol + j;
            ok[nt][j] = (col < Nn);
            bv[nt][j] = ok[nt][j] ? bias[col] : 0.f;
        }

    // pass 1: write out + row max
#pragma unroll
    for (int mt = 0; mt < 4; mt++) {
#pragma unroll
        for (int h = 0; h < 2; h++) {
            int lrow = wm + mt * 16 + crow + h * 8;
            int row = bm + lrow;
            float vmax = NEG_INF;
#pragma unroll
            for (int nt = 0; nt < 4; nt++)
#pragma unroll
                for (int j = 0; j < 2; j++) {
                    if (ok[nt][j]) {
                        float v = c[mt][nt][h * 2 + j] + bv[nt][j];
                        out[(size_t)row * Nn + (bn + wn + nt * 8 + ccol + j)] = v;
                        vmax = fmaxf(vmax, v);
                    }
                }
            vmax = fmaxf(vmax, __shfl_xor_sync(0xffffffff, vmax, 1));
            vmax = fmaxf(vmax, __shfl_xor_sync(0xffffffff, vmax, 2));
            if ((lane & 3) == 0) sm_pm[lrow * 4 + wnw] = vmax;
        }
    }
    __syncthreads();
    if (tid < 128) {
        float m = fmaxf(fmaxf(sm_pm[tid * 4], sm_pm[tid * 4 + 1]),
                        fmaxf(sm_pm[tid * 4 + 2], sm_pm[tid * 4 + 3]));
        sm_max[tid] = m;
    }
    __syncthreads();
    // pass 2: sumexp
#pragma unroll
    for (int mt = 0; mt < 4; mt++) {
#pragma unroll
        for (int h = 0; h < 2; h++) {
            int lrow = wm + mt * 16 + crow + h * 8;
            float M = sm_max[lrow];
            float ls = 0.f;
#pragma unroll
            for (int nt = 0; nt < 4; nt++)
#pragma unroll
                for (int j = 0; j < 2; j++)
                    if (ok[nt][j])
                        ls += __expf(c[mt][nt][h * 2 + j] + bv[nt][j] - M);
            ls += __shfl_xor_sync(0xffffffff, ls, 1);
            ls += __shfl_xor_sync(0xffffffff, ls, 2);
            if ((lane & 3) == 0) sm_ps[lrow * 4 + wnw] = ls;
        }
    }
    __syncthreads();
    if (tid < 128) {
        float s = sm_ps[tid * 4] + sm_ps[tid * 4 + 1] +
                  sm_ps[tid * 4 + 2] + sm_ps[tid * 4 + 3];
        g_pmax[(size_t)(bm + tid) * NT_TILES + blockIdx.x] = sm_max[tid];
        g_psum[(size_t)(bm + tid) * NT_TILES + blockIdx.x] = s;
    }
}

// merge per-tile partials into row LSE (one warp per row)
__global__ void k_reduce_lse() {
    int row = blockIdx.x * 8 + (threadIdx.x >> 5);
    int lane = threadIdx.x & 31;
    const float* pm = g_pmax + (size_t)row * NT_TILES;
    const float* ps = g_psum + (size_t)row * NT_TILES;
    float M = NEG_INF;
    for (int i = lane; i < NT_TILES; i += 32) M = fmaxf(M, pm[i]);
#pragma unroll
    for (int o = 16; o; o >>= 1) M = fmaxf(M, __shfl_xor_sync(0xffffffff, M, o));
    float S = 0.f;
    for (int i = lane; i < NT_TILES; i += 32) S += ps[i] * __expf(pm[i] - M);
#pragma unroll
    for (int o = 16; o; o >>= 1) S += __shfl_xor_sync(0xffffffff, S, o);
    if (lane == 0) g_lse[row] = M + logf(S);
}

__global__ void k_sub_lse(float* __restrict__ out) {
    int idx = blockIdx.x * blockDim.x + threadIdx.x;   // over BQ*12500 float4
    if (idx >= BQ * 12500) return;
    int row = idx / 12500;
    float l = g_lse[row];
    float4* p = (float4*)out + idx;
    float4 v = *p;
    v.x -= l; v.y -= l; v.z -= l; v.w -= l;
    *p = v;
}

// ================= per-node attention kernels =================
__global__ void k_attdot(const float* __restrict__ asrc, const float* __restrict__ adst) {
    int gt = blockIdx.x * blockDim.x + threadIdx.x;
    int node = gt >> 5;
    int lane = gt & 31;
    if (node >= N_NODES) return;
    float4 hv = *(const float4*)(g_h + (size_t)node * D + lane * 4);
    float4 s4 = *(const float4*)(asrc + lane * 4);
    float4 d4 = *(const float4*)(adst + lane * 4);
    float ds = hv.x * s4.x + hv.y * s4.y + hv.z * s4.z + hv.w * s4.w;
    float dd = hv.x * d4.x + hv.y * d4.y + hv.z * d4.z + hv.w * d4.w;
#pragma unroll
    for (int o = 16; o; o >>= 1) {
        ds += __shfl_down_sync(0xffffffff, ds, o);
        dd += __shfl_down_sync(0xffffffff, dd, o);
    }
    if (lane == 0) { g_as[node] = ds; g_ad[node] = dd; }
}

__global__ void k_node_attagg() {
    int gt = blockIdx.x * blockDim.x + threadIdx.x;
    int node = gt >> 5, lane = gt & 31;
    if (node >= N_NODES) return;
    int beg = g_off[node], end = g_off[node + 1];
    float ad = g_ad[node];

    float m = NEG_INF;
    for (int i = beg + lane; i < end; i += 32) {
        float s = g_as[g_srcl[i]] + ad;
        float e = (s > 0.f) ? s : 0.2f * s;
        g_e[i] = e;
        m = fmaxf(m, e);
    }
#pragma unroll
    for (int o = 16; o; o >>= 1) m = fmaxf(m, __shfl_xor_sync(0xffffffff, m, o));

    __syncwarp();
    float den = 0.f;
    for (int i = beg + lane; i < end; i += 32) {
        float ex = __expf(g_e[i] - m);
        g_e[i] = ex;
        den += ex;
    }
#pragma unroll
    for (int o = 16; o; o >>= 1) den += __shfl_xor_sync(0xffffffff, den, o);
    float inv = 1.f / den;
    __syncwarp();

    float4 acc = make_float4(0.f, 0.f, 0.f, 0.f);
    for (int i = beg; i < end; i++) {
        float w = g_e[i] * inv;
        int s = g_srcl[i];
        float4 hv = *(const float4*)(g_h + (size_t)s * D + lane * 4);
        acc.x += w * hv.x; acc.y += w * hv.y;
        acc.z += w * hv.z; acc.w += w * hv.w;
    }
    *(float4*)(g_agg + (size_t)node * D + lane * 4) = acc;
}

// ================= GraphNorm (single stats pass) =================
#define RPB 64
__global__ void k_zero_stats() {
    int d = threadIdx.x;
    g_musum[d] = 0.f; g_varsum[d] = 0.f;
}
__global__ void k_colstats() {
    int col = threadIdx.x;
    int r0 = blockIdx.x * RPB;
    int r1 = min(r0 + RPB, N_NODES);
    float s = 0.f, s2 = 0.f;
    for (int r = r0; r < r1; r++) {
        float a = g_agg[(size_t)r * D + col];
        s += a; s2 += a * a;
    }
    atomicAdd(&g_musum[col], s);
    atomicAdd(&g_varsum[col], s2);
}
__global__ void k_fin_stats(const float* __restrict__ bb, const float* __restrict__ ms) {
    int d = threadIdx.x;
    float S1 = g_musum[d] * (1.f / N_NODES);
    float S2 = g_varsum[d] * (1.f / N_NODES);
    float mu = S1 + bb[d];
    float cc = bb[d] - mu * ms[d];
    float var = S2 + 2.f * cc * S1 + cc * cc;
    g_mu[d] = mu;
    g_istd[d] = rsqrtf(var + EPSV);
}
__global__ void k_normalize(const float* __restrict__ bb, const float* __restrict__ gw,
                            const float* __restrict__ gb, const float* __restrict__ ms) {
    int idx = blockIdx.x * blockDim.x + threadIdx.x;
    if (idx >= N_NODES * D) return;
    int d = idx & (D - 1);
    float t = g_agg[idx] + bb[d] - g_mu[d] * ms[d];
    float v = t * g_istd[d] * gw[d] + gb[d];
    g_hn[idx] = v > 0.f ? v : 0.f;
}

// ================= head =================
__global__ void k_gather(const int* __restrict__ x) {
    int idx = blockIdx.x * blockDim.x + threadIdx.x;
    if (idx >= BQ * H3) return;
    int b = idx / H3;
    int rem = idx - b * H3;
    int j = rem >> 7;
    int d = rem & (D - 1);
    int node = x[b * 3 + j];
    g_z[idx] = g_hn[(size_t)node * D + d];
}

__global__ void k_bn_relu(const float* __restrict__ bw, const float* __restrict__ bb) {
    int c = blockIdx.x;
    int t = threadIdx.x;
    __shared__ float sm[256], ss[256];
    float s = 0.f, s2 = 0.f;
    for (int r = t; r < BQ; r += 256) {
        float v = g_z1[r * H3 + c];
        s += v; s2 += v * v;
    }
    sm[t] = s; ss[t] = s2;
    __syncthreads();
    for (int o = 128; o; o >>= 1) {
        if (t < o) { sm[t] += sm[t + o]; ss[t] += ss[t + o]; }
        __syncthreads();
    }
    float mu = sm[0] * (1.f / BQ);
    float var = ss[0] * (1.f / BQ) - mu * mu;
    float istd = rsqrtf(var + EPSV);
    float w = bw[c], bias = bb[c];
    for (int r = t; r < BQ; r += 256) {
        float v = (g_z1[r * H3 + c] - mu) * istd * w + bias;
        g_z2[r * H3 + c] = v > 0.f ? v : 0.f;
    }
}

// ================= host driver =================
static void run_gat_layer(const float* Aext, int asel, const float* W,
                          const float* asrc, const float* adst, const float* bb,
                          const float* gw, const float* gb, const float* gms)
{
    k_zero_stats<<<1, D>>>();
    dim3 g1(1, (N_NODES + 127) / 128);
    k_sgemm_nt<<<g1, 256>>>(Aext, W, nullptr, N_NODES, D, D, asel, /*csel=g_h*/1);
    k_attdot<<<(N_NODES * 32 + 255) / 256, 256>>>(asrc, adst);
    k_node_attagg<<<(N_NODES * 32 + 255) / 256, 256>>>();
    k_colstats<<<(N_NODES + RPB - 1) / RPB, D>>>();
    k_fin_stats<<<1, D>>>(bb, gms);
    k_normalize<<<(N_NODES * D + 255) / 256, 256>>>(bb, gw, gb, gms);
}

extern "C" void kernel_launch(void* const* d_in, const int* in_sizes, int n_in,
                              void* d_out, int out_size)
{
    const int*   x       = (const int*)  d_in[0];
    const int*   ei      = (const int*)  d_in[1];
    const float* emb     = (const float*)d_in[2];
    const float* W1      = (const float*)d_in[3];
    const float* asrc1   = (const float*)d_in[4];
    const float* adst1   = (const float*)d_in[5];
    const float* b1      = (const float*)d_in[6];
    const float* gn1w    = (const float*)d_in[7];
    const float* gn1b    = (const float*)d_in[8];
    const float* gn1ms   = (const float*)d_in[9];
    const float* W2      = (const float*)d_in[10];
    const float* asrc2   = (const float*)d_in[11];
    const float* adst2   = (const float*)d_in[12];
    const float* b2      = (const float*)d_in[13];
    const float* gn2w    = (const float*)d_in[14];
    const float* gn2b    = (const float*)d_in[15];
    const float* gn2ms   = (const float*)d_in[16];
    const float* lin1W   = (const float*)d_in[17];
    const float* lin1b   = (const float*)d_in[18];
    const float* bnw     = (const float*)d_in[19];
    const float* bnb     = (const float*)d_in[20];
    const float* lin2W   = (const float*)d_in[21];
    const float* lin2b   = (const float*)d_in[22];
    float* out = (float*)d_out;

    // opt in to 74KB dynamic smem for the mma kernel (idempotent)
    cudaFuncSetAttribute(k_mma_lin2, cudaFuncAttributeMaxDynamicSharedMemorySize,
                         MMA_SMEM_F * (int)sizeof(float));

    // --- CSR build ---
    k_zero_deg<<<(N_NODES + 255) / 256, 256>>>();
    k_count<<<(ET + 255) / 256, 256>>>(ei);
    k_scan<<<1, 1024>>>();
    k_copyoff<<<(N_NODES + 255) / 256, 256>>>();
    k_fill<<<(ET + 255) / 256, 256>>>(ei);

    // --- GAT layers ---
    run_gat_layer(emb, 0, W1, asrc1, adst1, b1, gn1w, gn1b, gn1ms);
    run_gat_layer(nullptr, 1, W2, asrc2, adst2, b2, gn2w, gn2b, gn2ms);

    // --- head ---
    k_gather<<<(BQ * H3 + 255) / 256, 256>>>(x);
    dim3 gz1((H3 + 127) / 128, (BQ + 127) / 128);
    k_sgemm_nt<<<gz1, 256>>>(nullptr, lin1W, lin1b, BQ, H3, H3, /*asel=g_z*/2, /*csel=g_z1*/2);
    k_bn_relu<<<H3, 256>>>(bnw, bnb);
    dim3 gz2(NT_TILES, BQ / 128);
    k_mma_lin2<<<gz2, 256, MMA_SMEM_F * sizeof(float)>>>(lin2W, lin2b, out);
    k_reduce_lse<<<BQ / 8, 256>>>();
    k_sub_lse<<<(BQ * 12500 + 255) / 256, 256>>>(out);
}

// round 5
// speedup vs baseline: 3.4503x; 1.3435x over previous
#include <cuda_runtime.h>
#include <cuda_bf16.h>
#include <math.h>
#include <stdint.h>

#define N_NODES 50000
#define N_EDGES 800000
#define ET (N_EDGES + N_NODES)
#define D 128
#define BQ 1024
#define H3 384
#define EPSV 1e-5f
#define NT_TILES 391             // ceil(50000/128)

#define NEG_INF (__int_as_float(0xff800000))

// ---------------- scratch (device globals; no allocation) ----------------
__device__ float g_h[N_NODES * D];
__device__ float g_agg[N_NODES * D];
__device__ float g_hn[N_NODES * D];
__device__ float g_as[N_NODES];
__device__ float g_ad[N_NODES];
__device__ float g_e[ET];
__device__ float g_musum[D];
__device__ float g_varsum[D];
__device__ float g_mu[D];
__device__ float g_istd[D];
__device__ float g_z[BQ * H3];
__device__ float g_z1[BQ * H3];
__device__ float g_lse[BQ];
__device__ float g_pmax[(size_t)BQ * NT_TILES];
__device__ float g_psum[(size_t)BQ * NT_TILES];
__device__ __nv_bfloat16 g_w16[(size_t)N_NODES * H3];   // bf16 lin2 weights
__device__ __nv_bfloat16 g_z16[BQ * H3];                // bf16 lin2 activations
// CSR
__device__ int g_deg[N_NODES];
__device__ int g_off[N_NODES + 1];
__device__ int g_cur[N_NODES];
__device__ int g_srcl[ET];

// ================= CSR build =================
__global__ void k_zero_deg() {
    int i = blockIdx.x * blockDim.x + threadIdx.x;
    if (i < N_NODES) g_deg[i] = 0;
}
__global__ void k_count(const int* __restrict__ ei) {
    int i = blockIdx.x * blockDim.x + threadIdx.x;
    if (i >= ET) return;
    int dst = (i < N_EDGES) ? ei[N_EDGES + i] : (i - N_EDGES);
    atomicAdd(&g_deg[dst], 1);
}
__global__ void k_scan() {
    __shared__ int swarp[32];
    __shared__ int carry;
    int tid = threadIdx.x;
    int lane = tid & 31, wid = tid >> 5;
    if (tid == 0) carry = 0;
    __syncthreads();
    for (int base = 0; base < N_NODES; base += 1024) {
        int v = (base + tid < N_NODES) ? g_deg[base + tid] : 0;
        int x = v;
#pragma unroll
        for (int o = 1; o < 32; o <<= 1) {
            int t = __shfl_up_sync(0xffffffff, x, o);
            if (lane >= o) x += t;
        }
        if (lane == 31) swarp[wid] = x;
        __syncthreads();
        if (wid == 0) {
            int y = swarp[lane];
#pragma unroll
            for (int o = 1; o < 32; o <<= 1) {
                int t = __shfl_up_sync(0xffffffff, y, o);
                if (lane >= o) y += t;
            }
            swarp[lane] = y;
        }
        __syncthreads();
        int prefix = (wid > 0) ? swarp[wid - 1] : 0;
        int incl = x + prefix;
        if (base + tid < N_NODES) g_off[base + tid] = carry + incl - v;
        __syncthreads();
        if (tid == 0) carry += swarp[31];
        __syncthreads();
    }
    if (tid == 0) g_off[N_NODES] = ET;
}
__global__ void k_copyoff() {
    int i = blockIdx.x * blockDim.x + threadIdx.x;
    if (i < N_NODES) g_cur[i] = g_off[i];
}
__global__ void k_fill(const int* __restrict__ ei) {
    int i = blockIdx.x * blockDim.x + threadIdx.x;
    if (i >= ET) return;
    int src, dst;
    if (i < N_EDGES) { src = ei[i]; dst = ei[N_EDGES + i]; }
    else { src = dst = i - N_EDGES; }
    int pos = atomicAdd(&g_cur[dst], 1);
    g_srcl[pos] = src;
}

// ================= weight conversion =================
__global__ void k_cvt_w(const float* __restrict__ W) {
    int i = blockIdx.x * blockDim.x + threadIdx.x;
    if (i >= N_NODES * H3 / 4) return;
    float4 v = ((const float4*)W)[i];
    __nv_bfloat162 lo = __floats2bfloat162_rn(v.x, v.y);
    __nv_bfloat162 hi = __floats2bfloat162_rn(v.z, v.w);
    ((__nv_bfloat162*)g_w16)[i * 2] = lo;
    ((__nv_bfloat162*)g_w16)[i * 2 + 1] = hi;
}

// ================= cp.async helpers =================
__device__ __forceinline__ void cp_async16(uint32_t saddr, const void* gptr, int srcBytes) {
    asm volatile("cp.async.cg.shared.global [%0], [%1], 16, %2;\n"
                 :: "r"(saddr), "l"(gptr), "r"(srcBytes));
}
__device__ __forceinline__ void cp_commit() {
    asm volatile("cp.async.commit_group;\n");
}
template <int NW>
__device__ __forceinline__ void cp_wait() {
    asm volatile("cp.async.wait_group %0;\n" :: "n"(NW));
}

// ================= mma wrappers =================
__device__ __forceinline__ void mma_tf32(float c[4], uint32_t a0, uint32_t a1,
                                         uint32_t a2, uint32_t a3,
                                         uint32_t b0, uint32_t b1) {
    asm volatile(
        "mma.sync.aligned.m16n8k8.row.col.f32.tf32.tf32.f32 "
        "{%0,%1,%2,%3}, {%4,%5,%6,%7}, {%8,%9}, {%0,%1,%2,%3};"
        : "+f"(c[0]), "+f"(c[1]), "+f"(c[2]), "+f"(c[3])
        : "r"(a0), "r"(a1), "r"(a2), "r"(a3), "r"(b0), "r"(b1));
}
__device__ __forceinline__ void mma_bf16(float c[4], uint32_t a0, uint32_t a1,
                                         uint32_t a2, uint32_t a3,
                                         uint32_t b0, uint32_t b1) {
    asm volatile(
        "mma.sync.aligned.m16n8k16.row.col.f32.bf16.bf16.f32 "
        "{%0,%1,%2,%3}, {%4,%5,%6,%7}, {%8,%9}, {%0,%1,%2,%3};"
        : "+f"(c[0]), "+f"(c[1]), "+f"(c[2]), "+f"(c[3])
        : "r"(a0), "r"(a1), "r"(a2), "r"(a3), "r"(b0), "r"(b1));
}

// ================= bf16 tensor-core GEMM for lin2 (+ fused LSE partials) ===
// out[BQ, N_NODES] = z16[BQ, H3] @ w16[N_NODES, H3]^T + bias
// BM=128, BN=128, BK=64; 2-stage cp.async; bf16 rows padded to 72
#define BPAD 72
#define BSTAGE (128 * BPAD)          // bf16 elems per operand-stage
#define LIN2_SMEM_B (4 * BSTAGE * 2) // bytes = 73728
__global__ __launch_bounds__(256) void k_mma_lin2(
    const float* __restrict__ bias, float* __restrict__ out)
{
    extern __shared__ __nv_bfloat16 smem16[];
    const int K = H3, Nn = N_NODES;
    __nv_bfloat16* Abuf = smem16;
    __nv_bfloat16* Bbuf = smem16 + 2 * BSTAGE;

    int tid = threadIdx.x;
    int warp = tid >> 5, lane = tid & 31;
    int wm = (warp & 1) * 64;
    int wnw = warp >> 1;
    int wn = wnw * 32;
    int bm = blockIdx.y * 128;
    int bn = blockIdx.x * 128;

    float c[4][4][4];
#pragma unroll
    for (int mt = 0; mt < 4; mt++)
#pragma unroll
        for (int nt = 0; nt < 4; nt++)
#pragma unroll
            for (int r = 0; r < 4; r++) c[mt][nt][r] = 0.f;

    int gr = lane >> 2, gc = lane & 3;

    auto load_tile = [&](int it, int stage) {
        int k0 = it * 64;
        __nv_bfloat16* Ad = Abuf + stage * BSTAGE;
        __nv_bfloat16* Bd = Bbuf + stage * BSTAGE;
#pragma unroll
        for (int l = 0; l < 4; l++) {
            int linear = tid + l * 256;      // 0..1023
            int row = linear >> 3;
            int kc = (linear & 7) * 8;       // bf16 elems
            uint32_t sa = (uint32_t)__cvta_generic_to_shared(Ad + row * BPAD + kc);
            cp_async16(sa, g_z16 + (size_t)(bm + row) * K + k0 + kc, 16);
            int grow = bn + row;
            int ok = (grow < Nn);
            uint32_t sb = (uint32_t)__cvta_generic_to_shared(Bd + row * BPAD + kc);
            cp_async16(sb, g_w16 + (size_t)(ok ? grow : 0) * K + k0 + kc, ok ? 16 : 0);
        }
        cp_commit();
    };

    const int NIT = K / 64;   // 6
    load_tile(0, 0);
    for (int it = 0; it < NIT; it++) {
        int cur = it & 1;
        if (it + 1 < NIT) { load_tile(it + 1, cur ^ 1); cp_wait<1>(); }
        else cp_wait<0>();
        __syncthreads();

        const __nv_bfloat16* Ac = Abuf + cur * BSTAGE;
        const __nv_bfloat16* Bc = Bbuf + cur * BSTAGE;
#pragma unroll
        for (int ks = 0; ks < 4; ks++) {
            int kb = ks * 16;
            uint32_t a[4][4];
#pragma unroll
            for (int mt = 0; mt < 4; mt++) {
                int mrow = wm + mt * 16 + gr;
                a[mt][0] = *(const uint32_t*)&Ac[mrow * BPAD + kb + gc * 2];
                a[mt][1] = *(const uint32_t*)&Ac[(mrow + 8) * BPAD + kb + gc * 2];
                a[mt][2] = *(const uint32_t*)&Ac[mrow * BPAD + kb + 8 + gc * 2];
                a[mt][3] = *(const uint32_t*)&Ac[(mrow + 8) * BPAD + kb + 8 + gc * 2];
            }
            uint32_t b[4][2];
#pragma unroll
            for (int nt = 0; nt < 4; nt++) {
                int ncol = wn + nt * 8 + gr;
                b[nt][0] = *(const uint32_t*)&Bc[ncol * BPAD + kb + gc * 2];
                b[nt][1] = *(const uint32_t*)&Bc[ncol * BPAD + kb + 8 + gc * 2];
            }
#pragma unroll
            for (int mt = 0; mt < 4; mt++)
#pragma unroll
                for (int nt = 0; nt < 4; nt++)
                    mma_bf16(c[mt][nt], a[mt][0], a[mt][1], a[mt][2], a[mt][3],
                             b[nt][0], b[nt][1]);
        }
        __syncthreads();
    }

    // ---- epilogue: bias + store + per-row (max, sumexp) partials ----
    float* smf   = (float*)smem16;
    float* sm_pm  = smf;               // [128][4]
    float* sm_max = smf + 512;         // [128]
    float* sm_ps  = smf + 512 + 128;   // [128][4]

    int crow = lane >> 2, ccol = (lane & 3) * 2;
    float bv[4][2];
    bool ok[4][2];
#pragma unroll
    for (int nt = 0; nt < 4; nt++)
#pragma unroll
        for (int j = 0; j < 2; j++) {
            int col = bn + wn + nt * 8 + ccol + j;
            ok[nt][j] = (col < Nn);
            bv[nt][j] = ok[nt][j] ? bias[col] : 0.f;
        }

#pragma unroll
    for (int mt = 0; mt < 4; mt++) {
#pragma unroll
        for (int h = 0; h < 2; h++) {
            int lrow = wm + mt * 16 + crow + h * 8;
            int row = bm + lrow;
            float vmax = NEG_INF;
#pragma unroll
            for (int nt = 0; nt < 4; nt++)
#pragma unroll
                for (int j = 0; j < 2; j++) {
                    if (ok[nt][j]) {
                        float v = c[mt][nt][h * 2 + j] + bv[nt][j];
                        out[(size_t)row * Nn + (bn + wn + nt * 8 + ccol + j)] = v;
                        vmax = fmaxf(vmax, v);
                    }
                }
            vmax = fmaxf(vmax, __shfl_xor_sync(0xffffffff, vmax, 1));
            vmax = fmaxf(vmax, __shfl_xor_sync(0xffffffff, vmax, 2));
            if ((lane & 3) == 0) sm_pm[lrow * 4 + wnw] = vmax;
        }
    }
    __syncthreads();
    if (tid < 128) {
        float m = fmaxf(fmaxf(sm_pm[tid * 4], sm_pm[tid * 4 + 1]),
                        fmaxf(sm_pm[tid * 4 + 2], sm_pm[tid * 4 + 3]));
        sm_max[tid] = m;
    }
    __syncthreads();
#pragma unroll
    for (int mt = 0; mt < 4; mt++) {
#pragma unroll
        for (int h = 0; h < 2; h++) {
            int lrow = wm + mt * 16 + crow + h * 8;
            float M = sm_max[lrow];
            float ls = 0.f;
#pragma unroll
            for (int nt = 0; nt < 4; nt++)
#pragma unroll
                for (int j = 0; j < 2; j++)
                    if (ok[nt][j])
                        ls += __expf(c[mt][nt][h * 2 + j] + bv[nt][j] - M);
            ls += __shfl_xor_sync(0xffffffff, ls, 1);
            ls += __shfl_xor_sync(0xffffffff, ls, 2);
            if ((lane & 3) == 0) sm_ps[lrow * 4 + wnw] = ls;
        }
    }
    __syncthreads();
    if (tid < 128) {
        float s = sm_ps[tid * 4] + sm_ps[tid * 4 + 1] +
                  sm_ps[tid * 4 + 2] + sm_ps[tid * 4 + 3];
        g_pmax[(size_t)(bm + tid) * NT_TILES + blockIdx.x] = sm_max[tid];
        g_psum[(size_t)(bm + tid) * NT_TILES + blockIdx.x] = s;
    }
}

// ================= tf32 tensor-core feature GEMM =================
// g_h[M,128] = A[M,128] @ W[128,128]^T ; A = emb or g_hn
#define MMA_PAD 36
#define MMA_STAGE_F (128 * MMA_PAD)
#define FEAT_SMEM_B (4 * MMA_STAGE_F * 4)   // 73728 bytes
__global__ __launch_bounds__(256) void k_mma_feat(
    const float* __restrict__ Aext, const float* __restrict__ W, int asel)
{
    extern __shared__ float smemf[];
    const float* A = asel ? g_hn : Aext;
    const int M = N_NODES, K = D;
    float* Abuf = smemf;
    float* Bbuf = smemf + 2 * MMA_STAGE_F;

    int tid = threadIdx.x;
    int warp = tid >> 5, lane = tid & 31;
    int wm = (warp & 1) * 64;
    int wn = (warp >> 1) * 32;
    int bm = blockIdx.y * 128;

    float c[4][4][4];
#pragma unroll
    for (int mt = 0; mt < 4; mt++)
#pragma unroll
        for (int nt = 0; nt < 4; nt++)
#pragma unroll
            for (int r = 0; r < 4; r++) c[mt][nt][r] = 0.f;

    int gr = lane >> 2, gc = lane & 3;

    auto load_tile = [&](int it, int stage) {
        int k0 = it * 32;
        float* Ad = Abuf + stage * MMA_STAGE_F;
        float* Bd = Bbuf + stage * MMA_STAGE_F;
#pragma unroll
        for (int l = 0; l < 4; l++) {
            int linear = tid + l * 256;
            int row = linear >> 3;
            int kc = (linear & 7) * 4;
            int ar = bm + row;
            int okA = (ar < M);
            uint32_t sa = (uint32_t)__cvta_generic_to_shared(Ad + row * MMA_PAD + kc);
            cp_async16(sa, A + (size_t)(okA ? ar : 0) * K + k0 + kc, okA ? 16 : 0);
            uint32_t sb = (uint32_t)__cvta_generic_to_shared(Bd + row * MMA_PAD + kc);
            cp_async16(sb, W + (size_t)row * K + k0 + kc, 16);
        }
        cp_commit();
    };

    const int NIT = K / 32;   // 4
    load_tile(0, 0);
    for (int it = 0; it < NIT; it++) {
        int cur = it & 1;
        if (it + 1 < NIT) { load_tile(it + 1, cur ^ 1); cp_wait<1>(); }
        else cp_wait<0>();
        __syncthreads();

        const float* Ac = Abuf + cur * MMA_STAGE_F;
        const float* Bc = Bbuf + cur * MMA_STAGE_F;
#pragma unroll
        for (int ks = 0; ks < 4; ks++) {
            int kb = ks * 8;
            uint32_t a[4][4];
#pragma unroll
            for (int mt = 0; mt < 4; mt++) {
                int mrow = wm + mt * 16 + gr;
                a[mt][0] = __float_as_uint(Ac[mrow * MMA_PAD + kb + gc]);
                a[mt][1] = __float_as_uint(Ac[(mrow + 8) * MMA_PAD + kb + gc]);
                a[mt][2] = __float_as_uint(Ac[mrow * MMA_PAD + kb + gc + 4]);
                a[mt][3] = __float_as_uint(Ac[(mrow + 8) * MMA_PAD + kb + gc + 4]);
            }
            uint32_t b[4][2];
#pragma unroll
            for (int nt = 0; nt < 4; nt++) {
                int ncol = wn + nt * 8 + gr;
                b[nt][0] = __float_as_uint(Bc[ncol * MMA_PAD + kb + gc]);
                b[nt][1] = __float_as_uint(Bc[ncol * MMA_PAD + kb + gc + 4]);
            }
#pragma unroll
            for (int mt = 0; mt < 4; mt++)
#pragma unroll
                for (int nt = 0; nt < 4; nt++)
                    mma_tf32(c[mt][nt], a[mt][0], a[mt][1], a[mt][2], a[mt][3],
                             b[nt][0], b[nt][1]);
        }
        __syncthreads();
    }

    int crow = lane >> 2, ccol = (lane & 3) * 2;
#pragma unroll
    for (int mt = 0; mt < 4; mt++) {
#pragma unroll
        for (int h = 0; h < 2; h++) {
            int row = bm + wm + mt * 16 + crow + h * 8;
            if (row >= M) continue;
#pragma unroll
            for (int nt = 0; nt < 4; nt++) {
                int col = wn + nt * 8 + ccol;
                g_h[(size_t)row * D + col]     = c[mt][nt][h * 2];
                g_h[(size_t)row * D + col + 1] = c[mt][nt][h * 2 + 1];
            }
        }
    }
}

// ================= fp32 SGEMM (lin1 only) =================
__global__ __launch_bounds__(256) void k_sgemm_nt(
    const float* __restrict__ Bm, const float* __restrict__ bias,
    int M, int Nn, int K)
{
    const float* A = g_z;
    float* C = g_z1;

    __shared__ float As[8][128];
    __shared__ float Bs[8][128];

    int tid = threadIdx.x;
    int tx = tid & 15, ty = tid >> 4;
    int bm = blockIdx.y * 128, bn = blockIdx.x * 128;

    float acc[8][8];
#pragma unroll
    for (int i = 0; i < 8; i++)
#pragma unroll
        for (int j = 0; j < 8; j++) acc[i][j] = 0.f;

    int lr = tid >> 1;
    int lk = (tid & 1) * 4;

    for (int k0 = 0; k0 < K; k0 += 8) {
        float4 a4 = make_float4(0.f, 0.f, 0.f, 0.f);
        int ar = bm + lr;
        if (ar < M) a4 = *(const float4*)(A + (size_t)ar * K + k0 + lk);
        As[lk + 0][lr] = a4.x; As[lk + 1][lr] = a4.y;
        As[lk + 2][lr] = a4.z; As[lk + 3][lr] = a4.w;

        float4 b4 = make_float4(0.f, 0.f, 0.f, 0.f);
        int br = bn + lr;
        if (br < Nn) b4 = *(const float4*)(Bm + (size_t)br * K + k0 + lk);
        Bs[lk + 0][lr] = b4.x; Bs[lk + 1][lr] = b4.y;
        Bs[lk + 2][lr] = b4.z; Bs[lk + 3][lr] = b4.w;
        __syncthreads();

#pragma unroll
        for (int k = 0; k < 8; k++) {
            float4 a0 = *(const float4*)&As[k][ty * 8];
            float4 a1 = *(const float4*)&As[k][ty * 8 + 4];
            float4 b0 = *(const float4*)&Bs[k][tx * 8];
            float4 b1 = *(const float4*)&Bs[k][tx * 8 + 4];
            float a[8] = {a0.x, a0.y, a0.z, a0.w, a1.x, a1.y, a1.z, a1.w};
            float b[8] = {b0.x, b0.y, b0.z, b0.w, b1.x, b1.y, b1.z, b1.w};
#pragma unroll
            for (int i = 0; i < 8; i++)
#pragma unroll
                for (int j = 0; j < 8; j++) acc[i][j] += a[i] * b[j];
        }
        __syncthreads();
    }

#pragma unroll
    for (int i = 0; i < 8; i++) {
        int row = bm + ty * 8 + i;
        if (row >= M) continue;
#pragma unroll
        for (int j = 0; j < 8; j++) {
            int col = bn + tx * 8 + j;
            if (col < Nn) C[(size_t)row * Nn + col] = acc[i][j] + bias[col];
        }
    }
}

// ================= LSE merge + subtract =================
__global__ void k_reduce_lse() {
    int row = blockIdx.x * 8 + (threadIdx.x >> 5);
    int lane = threadIdx.x & 31;
    const float* pm = g_pmax + (size_t)row * NT_TILES;
    const float* ps = g_psum + (size_t)row * NT_TILES;
    float M = NEG_INF;
    for (int i = lane; i < NT_TILES; i += 32) M = fmaxf(M, pm[i]);
#pragma unroll
    for (int o = 16; o; o >>= 1) M = fmaxf(M, __shfl_xor_sync(0xffffffff, M, o));
    float S = 0.f;
    for (int i = lane; i < NT_TILES; i += 32) S += ps[i] * __expf(pm[i] - M);
#pragma unroll
    for (int o = 16; o; o >>= 1) S += __shfl_xor_sync(0xffffffff, S, o);
    if (lane == 0) g_lse[row] = M + logf(S);
}

__global__ void k_sub_lse(float* __restrict__ out) {
    int idx = blockIdx.x * blockDim.x + threadIdx.x;
    if (idx >= BQ * 12500) return;
    int row = idx / 12500;
    float l = g_lse[row];
    float4* p = (float4*)out + idx;
    float4 v = *p;
    v.x -= l; v.y -= l; v.z -= l; v.w -= l;
    *p = v;
}

// ================= per-node attention =================
__global__ void k_attdot(const float* __restrict__ asrc, const float* __restrict__ adst) {
    int gt = blockIdx.x * blockDim.x + threadIdx.x;
    int node = gt >> 5;
    int lane = gt & 31;
    if (node >= N_NODES) return;
    float4 hv = *(const float4*)(g_h + (size_t)node * D + lane * 4);
    float4 s4 = *(const float4*)(asrc + lane * 4);
    float4 d4 = *(const float4*)(adst + lane * 4);
    float ds = hv.x * s4.x + hv.y * s4.y + hv.z * s4.z + hv.w * s4.w;
    float dd = hv.x * d4.x + hv.y * d4.y + hv.z * d4.z + hv.w * d4.w;
#pragma unroll
    for (int o = 16; o; o >>= 1) {
        ds += __shfl_down_sync(0xffffffff, ds, o);
        dd += __shfl_down_sync(0xffffffff, dd, o);
    }
    if (lane == 0) { g_as[node] = ds; g_ad[node] = dd; }
}

__global__ void k_node_attagg() {
    int gt = blockIdx.x * blockDim.x + threadIdx.x;
    int node = gt >> 5, lane = gt & 31;
    if (node >= N_NODES) return;
    int beg = g_off[node], end = g_off[node + 1];
    float ad = g_ad[node];

    float m = NEG_INF;
    for (int i = beg + lane; i < end; i += 32) {
        float s = g_as[g_srcl[i]] + ad;
        float e = (s > 0.f) ? s : 0.2f * s;
        g_e[i] = e;
        m = fmaxf(m, e);
    }
#pragma unroll
    for (int o = 16; o; o >>= 1) m = fmaxf(m, __shfl_xor_sync(0xffffffff, m, o));

    __syncwarp();
    float den = 0.f;
    for (int i = beg + lane; i < end; i += 32) {
        float ex = __expf(g_e[i] - m);
        g_e[i] = ex;
        den += ex;
    }
#pragma unroll
    for (int o = 16; o; o >>= 1) den += __shfl_xor_sync(0xffffffff, den, o);
    float inv = 1.f / den;
    __syncwarp();

    float4 acc = make_float4(0.f, 0.f, 0.f, 0.f);
    for (int i = beg; i < end; i++) {
        float w = g_e[i] * inv;
        int s = g_srcl[i];
        float4 hv = *(const float4*)(g_h + (size_t)s * D + lane * 4);
        acc.x += w * hv.x; acc.y += w * hv.y;
        acc.z += w * hv.z; acc.w += w * hv.w;
    }
    *(float4*)(g_agg + (size_t)node * D + lane * 4) = acc;
}

// ================= GraphNorm (single stats pass) =================
#define RPB 64
__global__ void k_zero_stats() {
    int d = threadIdx.x;
    g_musum[d] = 0.f; g_varsum[d] = 0.f;
}
__global__ void k_colstats() {
    int col = threadIdx.x;
    int r0 = blockIdx.x * RPB;
    int r1 = min(r0 + RPB, N_NODES);
    float s = 0.f, s2 = 0.f;
    for (int r = r0; r < r1; r++) {
        float a = g_agg[(size_t)r * D + col];
        s += a; s2 += a * a;
    }
    atomicAdd(&g_musum[col], s);
    atomicAdd(&g_varsum[col], s2);
}
__global__ void k_fin_stats(const float* __restrict__ bb, const float* __restrict__ ms) {
    int d = threadIdx.x;
    float S1 = g_musum[d] * (1.f / N_NODES);
    float S2 = g_varsum[d] * (1.f / N_NODES);
    float mu = S1 + bb[d];
    float cc = bb[d] - mu * ms[d];
    float var = S2 + 2.f * cc * S1 + cc * cc;
    g_mu[d] = mu;
    g_istd[d] = rsqrtf(var + EPSV);
}
__global__ void k_normalize(const float* __restrict__ bb, const float* __restrict__ gw,
                            const float* __restrict__ gb, const float* __restrict__ ms) {
    int idx = blockIdx.x * blockDim.x + threadIdx.x;
    if (idx >= N_NODES * D) return;
    int d = idx & (D - 1);
    float t = g_agg[idx] + bb[d] - g_mu[d] * ms[d];
    float v = t * g_istd[d] * gw[d] + gb[d];
    g_hn[idx] = v > 0.f ? v : 0.f;
}

// ================= head =================
__global__ void k_gather(const int* __restrict__ x) {
    int idx = blockIdx.x * blockDim.x + threadIdx.x;
    if (idx >= BQ * H3) return;
    int b = idx / H3;
    int rem = idx - b * H3;
    int j = rem >> 7;
    int d = rem & (D - 1);
    int node = x[b * 3 + j];
    g_z[idx] = g_hn[(size_t)node * D + d];
}

__global__ void k_bn_relu(const float* __restrict__ bw, const float* __restrict__ bb) {
    int c = blockIdx.x;
    int t = threadIdx.x;
    __shared__ float sm[256], ss[256];
    float s = 0.f, s2 = 0.f;
    for (int r = t; r < BQ; r += 256) {
        float v = g_z1[r * H3 + c];
        s += v; s2 += v * v;
    }
    sm[t] = s; ss[t] = s2;
    __syncthreads();
    for (int o = 128; o; o >>= 1) {
        if (t < o) { sm[t] += sm[t + o]; ss[t] += ss[t + o]; }
        __syncthreads();
    }
    float mu = sm[0] * (1.f / BQ);
    float var = ss[0] * (1.f / BQ) - mu * mu;
    float istd = rsqrtf(var + EPSV);
    float w = bw[c], bias = bb[c];
    for (int r = t; r < BQ; r += 256) {
        float v = (g_z1[r * H3 + c] - mu) * istd * w + bias;
        g_z16[r * H3 + c] = __float2bfloat16(v > 0.f ? v : 0.f);
    }
}

// ================= host driver =================
static void run_gat_layer(const float* Aext, int asel, const float* W,
                          const float* asrc, const float* adst, const float* bb,
                          const float* gw, const float* gb, const float* gms)
{
    k_zero_stats<<<1, D>>>();
    dim3 gf(1, NT_TILES);
    k_mma_feat<<<gf, 256, FEAT_SMEM_B>>>(Aext, W, asel);
    k_attdot<<<(N_NODES * 32 + 255) / 256, 256>>>(asrc, adst);
    k_node_attagg<<<(N_NODES * 32 + 255) / 256, 256>>>();
    k_colstats<<<(N_NODES + RPB - 1) / RPB, D>>>();
    k_fin_stats<<<1, D>>>(bb, gms);
    k_normalize<<<(N_NODES * D + 255) / 256, 256>>>(bb, gw, gb, gms);
}

extern "C" void kernel_launch(void* const* d_in, const int* in_sizes, int n_in,
                              void* d_out, int out_size)
{
    const int*   x       = (const int*)  d_in[0];
    const int*   ei      = (const int*)  d_in[1];
    const float* emb     = (const float*)d_in[2];
    const float* W1      = (const float*)d_in[3];
    const float* asrc1   = (const float*)d_in[4];
    const float* adst1   = (const float*)d_in[5];
    const float* b1      = (const float*)d_in[6];
    const float* gn1w    = (const float*)d_in[7];
    const float* gn1b    = (const float*)d_in[8];
    const float* gn1ms   = (const float*)d_in[9];
    const float* W2      = (const float*)d_in[10];
    const float* asrc2   = (const float*)d_in[11];
    const float* adst2   = (const float*)d_in[12];
    const float* b2      = (const float*)d_in[13];
    const float* gn2w    = (const float*)d_in[14];
    const float* gn2b    = (const float*)d_in[15];
    const float* gn2ms   = (const float*)d_in[16];
    const float* lin1W   = (const float*)d_in[17];
    const float* lin1b   = (const float*)d_in[18];
    const float* bnw     = (const float*)d_in[19];
    const float* bnb     = (const float*)d_in[20];
    const float* lin2W   = (const float*)d_in[21];
    const float* lin2b   = (const float*)d_in[22];
    float* out = (float*)d_out;

    cudaFuncSetAttribute(k_mma_lin2, cudaFuncAttributeMaxDynamicSharedMemorySize, LIN2_SMEM_B);
    cudaFuncSetAttribute(k_mma_feat, cudaFuncAttributeMaxDynamicSharedMemorySize, FEAT_SMEM_B);

    // --- W conversion + CSR build ---
    k_cvt_w<<<(N_NODES * H3 / 4 + 255) / 256, 256>>>(lin2W);
    k_zero_deg<<<(N_NODES + 255) / 256, 256>>>();
    k_count<<<(ET + 255) / 256, 256>>>(ei);
    k_scan<<<1, 1024>>>();
    k_copyoff<<<(N_NODES + 255) / 256, 256>>>();
    k_fill<<<(ET + 255) / 256, 256>>>(ei);

    // --- GAT layers ---
    run_gat_layer(emb, 0, W1, asrc1, adst1, b1, gn1w, gn1b, gn1ms);
    run_gat_layer(nullptr, 1, W2, asrc2, adst2, b2, gn2w, gn2b, gn2ms);

    // --- head ---
    k_gather<<<(BQ * H3 + 255) / 256, 256>>>(x);
    dim3 gz1((H3 + 127) / 128, (BQ + 127) / 128);
    k_sgemm_nt<<<gz1, 256>>>(lin1W, lin1b, BQ, H3, H3);
    k_bn_relu<<<H3, 256>>>(bnw, bnb);
    dim3 gz2(NT_TILES, BQ / 128);
    k_mma_lin2<<<gz2, 256, LIN2_SMEM_B>>>(lin2b, out);
    k_reduce_lse<<<BQ / 8, 256>>>();
    k_sub_lse<<<(BQ * 12500 + 255) / 256, 256>>>(out);
}

// round 6
// speedup vs baseline: 3.6661x; 1.0625x over previous
#include <cuda_runtime.h>
#include <cuda_bf16.h>
#include <math.h>
#include <stdint.h>

#define N_NODES 50000
#define N_EDGES 800000
#define ET (N_EDGES + N_NODES)
#define D 128
#define BQ 1024
#define H3 384
#define EPSV 1e-5f
#define NT_TILES 391             // ceil(50000/128)
#define NB_SCAN 196              // ceil(50000/256)

#define NEG_INF (__int_as_float(0xff800000))

// ---------------- scratch (device globals; no allocation) ----------------
__device__ float g_h[N_NODES * D];
__device__ float g_agg[N_NODES * D];
__device__ float g_hn[N_NODES * D];
__device__ float g_as[N_NODES];
__device__ float g_ad[N_NODES];
__device__ float g_e[ET];
__device__ float g_musum[D];
__device__ float g_varsum[D];
__device__ float g_mu[D];
__device__ float g_istd[D];
__device__ float g_z[BQ * H3];
__device__ float g_z1[BQ * H3];
__device__ float g_lse[BQ];
__device__ float g_pmax[(size_t)BQ * NT_TILES];
__device__ float g_psum[(size_t)BQ * NT_TILES];
__device__ __nv_bfloat16 g_w16[(size_t)N_NODES * H3];
__device__ __nv_bfloat16 g_z16[BQ * H3];
// CSR
__device__ int g_deg[N_NODES];
__device__ int g_off[N_NODES + 1];
__device__ int g_cur[N_NODES];
__device__ int g_srcl[ET];
__device__ int g_bsum[NB_SCAN];
__device__ int g_boff[NB_SCAN];

// ================= CSR build =================
__global__ void k_zero_deg() {
    int i = blockIdx.x * blockDim.x + threadIdx.x;
    if (i < N_NODES) g_deg[i] = 0;
}
__global__ void k_count(const int* __restrict__ ei) {
    int i = blockIdx.x * blockDim.x + threadIdx.x;
    if (i >= ET) return;
    int dst = (i < N_EDGES) ? ei[N_EDGES + i] : (i - N_EDGES);
    atomicAdd(&g_deg[dst], 1);
}
// phase 1: per-block sums of deg
__global__ void k_bsums() {
    int tid = threadIdx.x;
    int i = blockIdx.x * 256 + tid;
    int v = (i < N_NODES) ? g_deg[i] : 0;
    int lane = tid & 31, wid = tid >> 5;
#pragma unroll
    for (int o = 16; o; o >>= 1) v += __shfl_down_sync(0xffffffff, v, o);
    __shared__ int ws[8];
    if (lane == 0) ws[wid] = v;
    __syncthreads();
    if (tid == 0) {
        int s = 0;
#pragma unroll
        for (int w = 0; w < 8; w++) s += ws[w];
        g_bsum[blockIdx.x] = s;
    }
}
// phase 2: exclusive scan of 196 block sums (1 block)
__global__ void k_scan2() {
    int tid = threadIdx.x;
    int lane = tid & 31, wid = tid >> 5;
    int v = (tid < NB_SCAN) ? g_bsum[tid] : 0;
    int x = v;
#pragma unroll
    for (int o = 1; o < 32; o <<= 1) {
        int t = __shfl_up_sync(0xffffffff, x, o);
        if (lane >= o) x += t;
    }
    __shared__ int ws[8];
    if (lane == 31) ws[wid] = x;
    __syncthreads();
    if (wid == 0 && lane < 8) {
        int y = ws[lane];
#pragma unroll
        for (int o = 1; o < 8; o <<= 1) {
            int t = __shfl_up_sync(0xff, y, o);
            if (lane >= o) y += t;
        }
        ws[lane] = y;
    }
    __syncthreads();
    int prefix = wid ? ws[wid - 1] : 0;
    if (tid < NB_SCAN) g_boff[tid] = prefix + x - v;
}
// phase 3: in-block exclusive scan + block offset -> g_off, g_cur
__global__ void k_addback() {
    int tid = threadIdx.x;
    int i = blockIdx.x * 256 + tid;
    int v = (i < N_NODES) ? g_deg[i] : 0;
    int lane = tid & 31, wid = tid >> 5;
    int x = v;
#pragma unroll
    for (int o = 1; o < 32; o <<= 1) {
        int t = __shfl_up_sync(0xffffffff, x, o);
        if (lane >= o) x += t;
    }
    __shared__ int ws[8];
    if (lane == 31) ws[wid] = x;
    __syncthreads();
    if (wid == 0 && lane < 8) {
        int y = ws[lane];
#pragma unroll
        for (int o = 1; o < 8; o <<= 1) {
            int t = __shfl_up_sync(0xff, y, o);
            if (lane >= o) y += t;
        }
        ws[lane] = y;
    }
    __syncthreads();
    int prefix = (wid ? ws[wid - 1] : 0) + g_boff[blockIdx.x];
    int excl = prefix + x - v;
    if (i < N_NODES) { g_off[i] = excl; g_cur[i] = excl; }
    if (i == 0) g_off[N_NODES] = ET;
}
__global__ void k_fill(const int* __restrict__ ei) {
    int i = blockIdx.x * blockDim.x + threadIdx.x;
    if (i >= ET) return;
    int src, dst;
    if (i < N_EDGES) { src = ei[i]; dst = ei[N_EDGES + i]; }
    else { src = dst = i - N_EDGES; }
    int pos = atomicAdd(&g_cur[dst], 1);
    g_srcl[pos] = src;
}

// ================= weight conversion =================
__global__ void k_cvt_w(const float* __restrict__ W) {
    int i = blockIdx.x * blockDim.x + threadIdx.x;
    if (i >= N_NODES * H3 / 4) return;
    float4 v = ((const float4*)W)[i];
    __nv_bfloat162 lo = __floats2bfloat162_rn(v.x, v.y);
    __nv_bfloat162 hi = __floats2bfloat162_rn(v.z, v.w);
    ((__nv_bfloat162*)g_w16)[i * 2] = lo;
    ((__nv_bfloat162*)g_w16)[i * 2 + 1] = hi;
}

// ================= cp.async helpers =================
__device__ __forceinline__ void cp_async16(uint32_t saddr, const void* gptr, int srcBytes) {
    asm volatile("cp.async.cg.shared.global [%0], [%1], 16, %2;\n"
                 :: "r"(saddr), "l"(gptr), "r"(srcBytes));
}
__device__ __forceinline__ void cp_commit() {
    asm volatile("cp.async.commit_group;\n");
}
template <int NW>
__device__ __forceinline__ void cp_wait() {
    asm volatile("cp.async.wait_group %0;\n" :: "n"(NW));
}

// ================= mma wrappers =================
__device__ __forceinline__ void mma_tf32(float c[4], uint32_t a0, uint32_t a1,
                                         uint32_t a2, uint32_t a3,
                                         uint32_t b0, uint32_t b1) {
    asm volatile(
        "mma.sync.aligned.m16n8k8.row.col.f32.tf32.tf32.f32 "
        "{%0,%1,%2,%3}, {%4,%5,%6,%7}, {%8,%9}, {%0,%1,%2,%3};"
        : "+f"(c[0]), "+f"(c[1]), "+f"(c[2]), "+f"(c[3])
        : "r"(a0), "r"(a1), "r"(a2), "r"(a3), "r"(b0), "r"(b1));
}
__device__ __forceinline__ void mma_bf16(float c[4], uint32_t a0, uint32_t a1,
                                         uint32_t a2, uint32_t a3,
                                         uint32_t b0, uint32_t b1) {
    asm volatile(
        "mma.sync.aligned.m16n8k16.row.col.f32.bf16.bf16.f32 "
        "{%0,%1,%2,%3}, {%4,%5,%6,%7}, {%8,%9}, {%0,%1,%2,%3};"
        : "+f"(c[0]), "+f"(c[1]), "+f"(c[2]), "+f"(c[3])
        : "r"(a0), "r"(a1), "r"(a2), "r"(a3), "r"(b0), "r"(b1));
}

// ================= bf16 tensor-core GEMM for lin2 (+ fused LSE partials) ===
#define BPAD 72
#define BSTAGE (128 * BPAD)
#define LIN2_SMEM_B (4 * BSTAGE * 2)
__global__ __launch_bounds__(256) void k_mma_lin2(
    const float* __restrict__ bias, float* __restrict__ out)
{
    extern __shared__ __nv_bfloat16 smem16[];
    const int K = H3, Nn = N_NODES;
    __nv_bfloat16* Abuf = smem16;
    __nv_bfloat16* Bbuf = smem16 + 2 * BSTAGE;

    int tid = threadIdx.x;
    int warp = tid >> 5, lane = tid & 31;
    int wm = (warp & 1) * 64;
    int wnw = warp >> 1;
    int wn = wnw * 32;
    int bm = blockIdx.y * 128;
    int bn = blockIdx.x * 128;

    float c[4][4][4];
#pragma unroll
    for (int mt = 0; mt < 4; mt++)
#pragma unroll
        for (int nt = 0; nt < 4; nt++)
#pragma unroll
            for (int r = 0; r < 4; r++) c[mt][nt][r] = 0.f;

    int gr = lane >> 2, gc = lane & 3;

    auto load_tile = [&](int it, int stage) {
        int k0 = it * 64;
        __nv_bfloat16* Ad = Abuf + stage * BSTAGE;
        __nv_bfloat16* Bd = Bbuf + stage * BSTAGE;
#pragma unroll
        for (int l = 0; l < 4; l++) {
            int linear = tid + l * 256;
            int row = linear >> 3;
            int kc = (linear & 7) * 8;
            uint32_t sa = (uint32_t)__cvta_generic_to_shared(Ad + row * BPAD + kc);
            cp_async16(sa, g_z16 + (size_t)(bm + row) * K + k0 + kc, 16);
            int grow = bn + row;
            int ok = (grow < Nn);
            uint32_t sb = (uint32_t)__cvta_generic_to_shared(Bd + row * BPAD + kc);
            cp_async16(sb, g_w16 + (size_t)(ok ? grow : 0) * K + k0 + kc, ok ? 16 : 0);
        }
        cp_commit();
    };

    const int NIT = K / 64;
    load_tile(0, 0);
    for (int it = 0; it < NIT; it++) {
        int cur = it & 1;
        if (it + 1 < NIT) { load_tile(it + 1, cur ^ 1); cp_wait<1>(); }
        else cp_wait<0>();
        __syncthreads();

        const __nv_bfloat16* Ac = Abuf + cur * BSTAGE;
        const __nv_bfloat16* Bc = Bbuf + cur * BSTAGE;
#pragma unroll
        for (int ks = 0; ks < 4; ks++) {
            int kb = ks * 16;
            uint32_t a[4][4];
#pragma unroll
            for (int mt = 0; mt < 4; mt++) {
                int mrow = wm + mt * 16 + gr;
                a[mt][0] = *(const uint32_t*)&Ac[mrow * BPAD + kb + gc * 2];
                a[mt][1] = *(const uint32_t*)&Ac[(mrow + 8) * BPAD + kb + gc * 2];
                a[mt][2] = *(const uint32_t*)&Ac[mrow * BPAD + kb + 8 + gc * 2];
                a[mt][3] = *(const uint32_t*)&Ac[(mrow + 8) * BPAD + kb + 8 + gc * 2];
            }
            uint32_t b[4][2];
#pragma unroll
            for (int nt = 0; nt < 4; nt++) {
                int ncol = wn + nt * 8 + gr;
                b[nt][0] = *(const uint32_t*)&Bc[ncol * BPAD + kb + gc * 2];
                b[nt][1] = *(const uint32_t*)&Bc[ncol * BPAD + kb + 8 + gc * 2];
            }
#pragma unroll
            for (int mt = 0; mt < 4; mt++)
#pragma unroll
                for (int nt = 0; nt < 4; nt++)
                    mma_bf16(c[mt][nt], a[mt][0], a[mt][1], a[mt][2], a[mt][3],
                             b[nt][0], b[nt][1]);
        }
        __syncthreads();
    }

    float* smf   = (float*)smem16;
    float* sm_pm  = smf;
    float* sm_max = smf + 512;
    float* sm_ps  = smf + 512 + 128;

    int crow = lane >> 2, ccol = (lane & 3) * 2;
    float bv[4][2];
    bool ok[4][2];
#pragma unroll
    for (int nt = 0; nt < 4; nt++)
#pragma unroll
        for (int j = 0; j < 2; j++) {
            int col = bn + wn + nt * 8 + ccol + j;
            ok[nt][j] = (col < Nn);
            bv[nt][j] = ok[nt][j] ? bias[col] : 0.f;
        }

#pragma unroll
    for (int mt = 0; mt < 4; mt++) {
#pragma unroll
        for (int h = 0; h < 2; h++) {
            int lrow = wm + mt * 16 + crow + h * 8;
            int row = bm + lrow;
            float vmax = NEG_INF;
#pragma unroll
            for (int nt = 0; nt < 4; nt++)
#pragma unroll
                for (int j = 0; j < 2; j++) {
                    if (ok[nt][j]) {
                        float v = c[mt][nt][h * 2 + j] + bv[nt][j];
                        out[(size_t)row * Nn + (bn + wn + nt * 8 + ccol + j)] = v;
                        vmax = fmaxf(vmax, v);
                    }
                }
            vmax = fmaxf(vmax, __shfl_xor_sync(0xffffffff, vmax, 1));
            vmax = fmaxf(vmax, __shfl_xor_sync(0xffffffff, vmax, 2));
            if ((lane & 3) == 0) sm_pm[lrow * 4 + wnw] = vmax;
        }
    }
    __syncthreads();
    if (tid < 128) {
        float m = fmaxf(fmaxf(sm_pm[tid * 4], sm_pm[tid * 4 + 1]),
                        fmaxf(sm_pm[tid * 4 + 2], sm_pm[tid * 4 + 3]));
        sm_max[tid] = m;
    }
    __syncthreads();
#pragma unroll
    for (int mt = 0; mt < 4; mt++) {
#pragma unroll
        for (int h = 0; h < 2; h++) {
            int lrow = wm + mt * 16 + crow + h * 8;
            float M = sm_max[lrow];
            float ls = 0.f;
#pragma unroll
            for (int nt = 0; nt < 4; nt++)
#pragma unroll
                for (int j = 0; j < 2; j++)
                    if (ok[nt][j])
                        ls += __expf(c[mt][nt][h * 2 + j] + bv[nt][j] - M);
            ls += __shfl_xor_sync(0xffffffff, ls, 1);
            ls += __shfl_xor_sync(0xffffffff, ls, 2);
            if ((lane & 3) == 0) sm_ps[lrow * 4 + wnw] = ls;
        }
    }
    __syncthreads();
    if (tid < 128) {
        float s = sm_ps[tid * 4] + sm_ps[tid * 4 + 1] +
                  sm_ps[tid * 4 + 2] + sm_ps[tid * 4 + 3];
        g_pmax[(size_t)(bm + tid) * NT_TILES + blockIdx.x] = sm_max[tid];
        g_psum[(size_t)(bm + tid) * NT_TILES + blockIdx.x] = s;
    }
}

// ================= tf32 tensor-core feature GEMM =================
#define MMA_PAD 36
#define MMA_STAGE_F (128 * MMA_PAD)
#define FEAT_SMEM_B (4 * MMA_STAGE_F * 4)
__global__ __launch_bounds__(256) void k_mma_feat(
    const float* __restrict__ Aext, const float* __restrict__ W, int asel)
{
    extern __shared__ float smemf[];
    const float* A = asel ? g_hn : Aext;
    const int M = N_NODES, K = D;
    float* Abuf = smemf;
    float* Bbuf = smemf + 2 * MMA_STAGE_F;

    int tid = threadIdx.x;
    int warp = tid >> 5, lane = tid & 31;
    int wm = (warp & 1) * 64;
    int wn = (warp >> 1) * 32;
    int bm = blockIdx.y * 128;

    float c[4][4][4];
#pragma unroll
    for (int mt = 0; mt < 4; mt++)
#pragma unroll
        for (int nt = 0; nt < 4; nt++)
#pragma unroll
            for (int r = 0; r < 4; r++) c[mt][nt][r] = 0.f;

    int gr = lane >> 2, gc = lane & 3;

    auto load_tile = [&](int it, int stage) {
        int k0 = it * 32;
        float* Ad = Abuf + stage * MMA_STAGE_F;
        float* Bd = Bbuf + stage * MMA_STAGE_F;
#pragma unroll
        for (int l = 0; l < 4; l++) {
            int linear = tid + l * 256;
            int row = linear >> 3;
            int kc = (linear & 7) * 4;
            int ar = bm + row;
            int okA = (ar < M);
            uint32_t sa = (uint32_t)__cvta_generic_to_shared(Ad + row * MMA_PAD + kc);
            cp_async16(sa, A + (size_t)(okA ? ar : 0) * K + k0 + kc, okA ? 16 : 0);
            uint32_t sb = (uint32_t)__cvta_generic_to_shared(Bd + row * MMA_PAD + kc);
            cp_async16(sb, W + (size_t)row * K + k0 + kc, 16);
        }
        cp_commit();
    };

    const int NIT = K / 32;
    load_tile(0, 0);
    for (int it = 0; it < NIT; it++) {
        int cur = it & 1;
        if (it + 1 < NIT) { load_tile(it + 1, cur ^ 1); cp_wait<1>(); }
        else cp_wait<0>();
        __syncthreads();

        const float* Ac = Abuf + cur * MMA_STAGE_F;
        const float* Bc = Bbuf + cur * MMA_STAGE_F;
#pragma unroll
        for (int ks = 0; ks < 4; ks++) {
            int kb = ks * 8;
            uint32_t a[4][4];
#pragma unroll
            for (int mt = 0; mt < 4; mt++) {
                int mrow = wm + mt * 16 + gr;
                a[mt][0] = __float_as_uint(Ac[mrow * MMA_PAD + kb + gc]);
                a[mt][1] = __float_as_uint(Ac[(mrow + 8) * MMA_PAD + kb + gc]);
                a[mt][2] = __float_as_uint(Ac[mrow * MMA_PAD + kb + gc + 4]);
                a[mt][3] = __float_as_uint(Ac[(mrow + 8) * MMA_PAD + kb + gc + 4]);
            }
            uint32_t b[4][2];
#pragma unroll
            for (int nt = 0; nt < 4; nt++) {
                int ncol = wn + nt * 8 + gr;
                b[nt][0] = __float_as_uint(Bc[ncol * MMA_PAD + kb + gc]);
                b[nt][1] = __float_as_uint(Bc[ncol * MMA_PAD + kb + gc + 4]);
            }
#pragma unroll
            for (int mt = 0; mt < 4; mt++)
#pragma unroll
                for (int nt = 0; nt < 4; nt++)
                    mma_tf32(c[mt][nt], a[mt][0], a[mt][1], a[mt][2], a[mt][3],
                             b[nt][0], b[nt][1]);
        }
        __syncthreads();
    }

    int crow = lane >> 2, ccol = (lane & 3) * 2;
#pragma unroll
    for (int mt = 0; mt < 4; mt++) {
#pragma unroll
        for (int h = 0; h < 2; h++) {
            int row = bm + wm + mt * 16 + crow + h * 8;
            if (row >= M) continue;
#pragma unroll
            for (int nt = 0; nt < 4; nt++) {
                int col = wn + nt * 8 + ccol;
                g_h[(size_t)row * D + col]     = c[mt][nt][h * 2];
                g_h[(size_t)row * D + col + 1] = c[mt][nt][h * 2 + 1];
            }
        }
    }
}

// ================= fp32 SGEMM (lin1 only) =================
__global__ __launch_bounds__(256) void k_sgemm_nt(
    const float* __restrict__ Bm, const float* __restrict__ bias,
    int M, int Nn, int K)
{
    const float* A = g_z;
    float* C = g_z1;

    __shared__ float As[8][128];
    __shared__ float Bs[8][128];

    int tid = threadIdx.x;
    int tx = tid & 15, ty = tid >> 4;
    int bm = blockIdx.y * 128, bn = blockIdx.x * 128;

    float acc[8][8];
#pragma unroll
    for (int i = 0; i < 8; i++)
#pragma unroll
        for (int j = 0; j < 8; j++) acc[i][j] = 0.f;

    int lr = tid >> 1;
    int lk = (tid & 1) * 4;

    for (int k0 = 0; k0 < K; k0 += 8) {
        float4 a4 = make_float4(0.f, 0.f, 0.f, 0.f);
        int ar = bm + lr;
        if (ar < M) a4 = *(const float4*)(A + (size_t)ar * K + k0 + lk);
        As[lk + 0][lr] = a4.x; As[lk + 1][lr] = a4.y;
        As[lk + 2][lr] = a4.z; As[lk + 3][lr] = a4.w;

        float4 b4 = make_float4(0.f, 0.f, 0.f, 0.f);
        int br = bn + lr;
        if (br < Nn) b4 = *(const float4*)(Bm + (size_t)br * K + k0 + lk);
        Bs[lk + 0][lr] = b4.x; Bs[lk + 1][lr] = b4.y;
        Bs[lk + 2][lr] = b4.z; Bs[lk + 3][lr] = b4.w;
        __syncthreads();

#pragma unroll
        for (int k = 0; k < 8; k++) {
            float4 a0 = *(const float4*)&As[k][ty * 8];
            float4 a1 = *(const float4*)&As[k][ty * 8 + 4];
            float4 b0 = *(const float4*)&Bs[k][tx * 8];
            float4 b1 = *(const float4*)&Bs[k][tx * 8 + 4];
            float a[8] = {a0.x, a0.y, a0.z, a0.w, a1.x, a1.y, a1.z, a1.w};
            float b[8] = {b0.x, b0.y, b0.z, b0.w, b1.x, b1.y, b1.z, b1.w};
#pragma unroll
            for (int i = 0; i < 8; i++)
#pragma unroll
                for (int j = 0; j < 8; j++) acc[i][j] += a[i] * b[j];
        }
        __syncthreads();
    }

#pragma unroll
    for (int i = 0; i < 8; i++) {
        int row = bm + ty * 8 + i;
        if (row >= M) continue;
#pragma unroll
        for (int j = 0; j < 8; j++) {
            int col = bn + tx * 8 + j;
            if (col < Nn) C[(size_t)row * Nn + col] = acc[i][j] + bias[col];
        }
    }
}

// ================= LSE merge + subtract =================
__global__ void k_reduce_lse() {
    int row = blockIdx.x * 8 + (threadIdx.x >> 5);
    int lane = threadIdx.x & 31;
    const float* pm = g_pmax + (size_t)row * NT_TILES;
    const float* ps = g_psum + (size_t)row * NT_TILES;
    float M = NEG_INF;
    for (int i = lane; i < NT_TILES; i += 32) M = fmaxf(M, pm[i]);
#pragma unroll
    for (int o = 16; o; o >>= 1) M = fmaxf(M, __shfl_xor_sync(0xffffffff, M, o));
    float S = 0.f;
    for (int i = lane; i < NT_TILES; i += 32) S += ps[i] * __expf(pm[i] - M);
#pragma unroll
    for (int o = 16; o; o >>= 1) S += __shfl_xor_sync(0xffffffff, S, o);
    if (lane == 0) g_lse[row] = M + logf(S);
}

__global__ void k_sub_lse(float* __restrict__ out) {
    int idx = blockIdx.x * blockDim.x + threadIdx.x;
    if (idx >= BQ * 12500) return;
    int row = idx / 12500;
    float l = g_lse[row];
    float4* p = (float4*)out + idx;
    float4 v = *p;
    v.x -= l; v.y -= l; v.z -= l; v.w -= l;
    *p = v;
}

// ================= per-node attention =================
__global__ void k_attdot(const float* __restrict__ asrc, const float* __restrict__ adst) {
    int gt = blockIdx.x * blockDim.x + threadIdx.x;
    int node = gt >> 5;
    int lane = gt & 31;
    if (node >= N_NODES) return;
    float4 hv = *(const float4*)(g_h + (size_t)node * D + lane * 4);
    float4 s4 = *(const float4*)(asrc + lane * 4);
    float4 d4 = *(const float4*)(adst + lane * 4);
    float ds = hv.x * s4.x + hv.y * s4.y + hv.z * s4.z + hv.w * s4.w;
    float dd = hv.x * d4.x + hv.y * d4.y + hv.z * d4.z + hv.w * d4.w;
#pragma unroll
    for (int o = 16; o; o >>= 1) {
        ds += __shfl_down_sync(0xffffffff, ds, o);
        dd += __shfl_down_sync(0xffffffff, dd, o);
    }
    if (lane == 0) { g_as[node] = ds; g_ad[node] = dd; }
}

__global__ void k_node_attagg() {
    int gt = blockIdx.x * blockDim.x + threadIdx.x;
    int node = gt >> 5, lane = gt & 31;
    if (node >= N_NODES) return;
    int beg = g_off[node], end = g_off[node + 1];
    float ad = g_ad[node];

    float m = NEG_INF;
    for (int i = beg + lane; i < end; i += 32) {
        float s = g_as[g_srcl[i]] + ad;
        float e = (s > 0.f) ? s : 0.2f * s;
        g_e[i] = e;
        m = fmaxf(m, e);
    }
#pragma unroll
    for (int o = 16; o; o >>= 1) m = fmaxf(m, __shfl_xor_sync(0xffffffff, m, o));

    __syncwarp();
    float den = 0.f;
    for (int i = beg + lane; i < end; i += 32) {
        float ex = __expf(g_e[i] - m);
        g_e[i] = ex;
        den += ex;
    }
#pragma unroll
    for (int o = 16; o; o >>= 1) den += __shfl_xor_sync(0xffffffff, den, o);
    float inv = 1.f / den;
    __syncwarp();

    float4 acc = make_float4(0.f, 0.f, 0.f, 0.f);
    int i = beg;
    for (; i + 1 < end; i += 2) {
        float w0 = g_e[i] * inv, w1 = g_e[i + 1] * inv;
        int s0 = g_srcl[i], s1 = g_srcl[i + 1];
        float4 h0 = *(const float4*)(g_h + (size_t)s0 * D + lane * 4);
        float4 h1 = *(const float4*)(g_h + (size_t)s1 * D + lane * 4);
        acc.x += w0 * h0.x + w1 * h1.x;
        acc.y += w0 * h0.y + w1 * h1.y;
        acc.z += w0 * h0.z + w1 * h1.z;
        acc.w += w0 * h0.w + w1 * h1.w;
    }
    if (i < end) {
        float w = g_e[i] * inv;
        int s = g_srcl[i];
        float4 hv = *(const float4*)(g_h + (size_t)s * D + lane * 4);
        acc.x += w * hv.x; acc.y += w * hv.y;
        acc.z += w * hv.z; acc.w += w * hv.w;
    }
    *(float4*)(g_agg + (size_t)node * D + lane * 4) = acc;
}

// ================= GraphNorm (single stats pass) =================
#define RPB 64
__global__ void k_zero_stats() {
    int d = threadIdx.x;
    g_musum[d] = 0.f; g_varsum[d] = 0.f;
}
__global__ void k_colstats() {
    int col = threadIdx.x;
    int r0 = blockIdx.x * RPB;
    int r1 = min(r0 + RPB, N_NODES);
    float s = 0.f, s2 = 0.f;
    for (int r = r0; r < r1; r++) {
        float a = g_agg[(size_t)r * D + col];
        s += a; s2 += a * a;
    }
    atomicAdd(&g_musum[col], s);
    atomicAdd(&g_varsum[col], s2);
}
__global__ void k_fin_stats(const float* __restrict__ bb, const float* __restrict__ ms) {
    int d = threadIdx.x;
    float S1 = g_musum[d] * (1.f / N_NODES);
    float S2 = g_varsum[d] * (1.f / N_NODES);
    float mu = S1 + bb[d];
    float cc = bb[d] - mu * ms[d];
    float var = S2 + 2.f * cc * S1 + cc * cc;
    g_mu[d] = mu;
    g_istd[d] = rsqrtf(var + EPSV);
}
__global__ void k_normalize(const float* __restrict__ bb, const float* __restrict__ gw,
                            const float* __restrict__ gb, const float* __restrict__ ms) {
    int idx = blockIdx.x * blockDim.x + threadIdx.x;
    if (idx >= N_NODES * D) return;
    int d = idx & (D - 1);
    float t = g_agg[idx] + bb[d] - g_mu[d] * ms[d];
    float v = t * g_istd[d] * gw[d] + gb[d];
    g_hn[idx] = v > 0.f ? v : 0.f;
}

// ================= head =================
__global__ void k_gather(const int* __restrict__ x) {
    int idx = blockIdx.x * blockDim.x + threadIdx.x;
    if (idx >= BQ * H3) return;
    int b = idx / H3;
    int rem = idx - b * H3;
    int j = rem >> 7;
    int d = rem & (D - 1);
    int node = x[b * 3 + j];
    g_z[idx] = g_hn[(size_t)node * D + d];
}

__global__ void k_bn_relu(const float* __restrict__ bw, const float* __restrict__ bb) {
    int c = blockIdx.x;
    int t = threadIdx.x;
    __shared__ float sm[256], ss[256];
    float s = 0.f, s2 = 0.f;
    for (int r = t; r < BQ; r += 256) {
        float v = g_z1[r * H3 + c];
        s += v; s2 += v * v;
    }
    sm[t] = s; ss[t] = s2;
    __syncthreads();
    for (int o = 128; o; o >>= 1) {
        if (t < o) { sm[t] += sm[t + o]; ss[t] += ss[t + o]; }
        __syncthreads();
    }
    float mu = sm[0] * (1.f / BQ);
    float var = ss[0] * (1.f / BQ) - mu * mu;
    float istd = rsqrtf(var + EPSV);
    float w = bw[c], bias = bb[c];
    for (int r = t; r < BQ; r += 256) {
        float v = (g_z1[r * H3 + c] - mu) * istd * w + bias;
        g_z16[r * H3 + c] = __float2bfloat16(v > 0.f ? v : 0.f);
    }
}

// ================= host driver =================
extern "C" void kernel_launch(void* const* d_in, const int* in_sizes, int n_in,
                              void* d_out, int out_size)
{
    const int*   x       = (const int*)  d_in[0];
    const int*   ei      = (const int*)  d_in[1];
    const float* emb     = (const float*)d_in[2];
    const float* W1      = (const float*)d_in[3];
    const float* asrc1   = (const float*)d_in[4];
    const float* adst1   = (const float*)d_in[5];
    const float* b1      = (const float*)d_in[6];
    const float* gn1w    = (const float*)d_in[7];
    const float* gn1b    = (const float*)d_in[8];
    const float* gn1ms   = (const float*)d_in[9];
    const float* W2      = (const float*)d_in[10];
    const float* asrc2   = (const float*)d_in[11];
    const float* adst2   = (const float*)d_in[12];
    const float* b2      = (const float*)d_in[13];
    const float* gn2w    = (const float*)d_in[14];
    const float* gn2b    = (const float*)d_in[15];
    const float* gn2ms   = (const float*)d_in[16];
    const float* lin1W   = (const float*)d_in[17];
    const float* lin1b   = (const float*)d_in[18];
    const float* bnw     = (const float*)d_in[19];
    const float* bnb     = (const float*)d_in[20];
    const float* lin2W   = (const float*)d_in[21];
    const float* lin2b   = (const float*)d_in[22];
    float* out = (float*)d_out;

    cudaFuncSetAttribute(k_mma_lin2, cudaFuncAttributeMaxDynamicSharedMemorySize, LIN2_SMEM_B);
    cudaFuncSetAttribute(k_mma_feat, cudaFuncAttributeMaxDynamicSharedMemorySize, FEAT_SMEM_B);

    dim3 gf(1, NT_TILES);

    // launches 1-5 (independent prep), 6 = k_mma_feat (profiled by ncu -s 5 -c 1)
    k_cvt_w<<<(N_NODES * H3 / 4 + 255) / 256, 256>>>(lin2W);         // 1
    k_zero_deg<<<(N_NODES + 255) / 256, 256>>>();                    // 2
    k_count<<<(ET + 255) / 256, 256>>>(ei);                          // 3
    k_zero_stats<<<1, D>>>();                                        // 4
    k_bsums<<<NB_SCAN, 256>>>();                                     // 5
    k_mma_feat<<<gf, 256, FEAT_SMEM_B>>>(emb, W1, 0);                // 6 (layer1)
    k_scan2<<<1, 256>>>();                                           // 7
    k_addback<<<NB_SCAN, 256>>>();                                   // 8
    k_fill<<<(ET + 255) / 256, 256>>>(ei);                           // 9

    // --- layer 1 rest ---
    k_attdot<<<(N_NODES * 32 + 255) / 256, 256>>>(asrc1, adst1);
    k_node_attagg<<<(N_NODES * 32 + 255) / 256, 256>>>();
    k_colstats<<<(N_NODES + RPB - 1) / RPB, D>>>();
    k_fin_stats<<<1, D>>>(b1, gn1ms);
    k_normalize<<<(N_NODES * D + 255) / 256, 256>>>(b1, gn1w, gn1b, gn1ms);

    // --- layer 2 ---
    k_zero_stats<<<1, D>>>();
    k_mma_feat<<<gf, 256, FEAT_SMEM_B>>>(nullptr, W2, 1);
    k_attdot<<<(N_NODES * 32 + 255) / 256, 256>>>(asrc2, adst2);
    k_node_attagg<<<(N_NODES * 32 + 255) / 256, 256>>>();
    k_colstats<<<(N_NODES + RPB - 1) / RPB, D>>>();
    k_fin_stats<<<1, D>>>(b2, gn2ms);
    k_normalize<<<(N_NODES * D + 255) / 256, 256>>>(b2, gn2w, gn2b, gn2ms);

    // --- head ---
    k_gather<<<(BQ * H3 + 255) / 256, 256>>>(x);
    dim3 gz1((H3 + 127) / 128, (BQ + 127) / 128);
    k_sgemm_nt<<<gz1, 256>>>(lin1W, lin1b, BQ, H3, H3);
    k_bn_relu<<<H3, 256>>>(bnw, bnb);
    dim3 gz2(NT_TILES, BQ / 128);
    k_mma_lin2<<<gz2, 256, LIN2_SMEM_B>>>(lin2b, out);
    k_reduce_lse<<<BQ / 8, 256>>>();
    k_sub_lse<<<(BQ * 12500 + 255) / 256, 256>>>(out);
}

// round 7
// speedup vs baseline: 3.7880x; 1.0333x over previous
#include <cuda_runtime.h>
#include <cuda_bf16.h>
#include <math.h>
#include <stdint.h>

#define N_NODES 50000
#define N_EDGES 800000
#define ET (N_EDGES + N_NODES)
#define D 128
#define BQ 1024
#define H3 384
#define EPSV 1e-5f
#define NT_TILES 391             // ceil(50000/128)
#define NB_SCAN 196              // ceil(50000/256)

#define NEG_INF (__int_as_float(0xff800000))

// ---------------- scratch (device globals; no allocation) ----------------
__device__ float g_h[N_NODES * D];
__device__ float g_agg[N_NODES * D];
__device__ float g_hn[N_NODES * D];
__device__ float g_as[N_NODES];
__device__ float g_ad[N_NODES];
__device__ float g_e[ET];
__device__ float g_musum2[2 * D];
__device__ float g_varsum2[2 * D];
__device__ float g_z1[BQ * H3];
__device__ float g_lse[BQ];
__device__ float g_pmax[(size_t)BQ * NT_TILES];
__device__ float g_psum[(size_t)BQ * NT_TILES];
__device__ __nv_bfloat16 g_w16[(size_t)N_NODES * H3];
__device__ __nv_bfloat16 g_z16[BQ * H3];
// CSR
__device__ int g_deg[N_NODES];
__device__ int g_off[N_NODES + 1];
__device__ int g_cur[N_NODES];
__device__ int g_srcl[ET];
__device__ int g_bsum[NB_SCAN];
__device__ int g_boff[NB_SCAN];

// ================= CSR build =================
__global__ void k_zero_deg() {
    int i = blockIdx.x * blockDim.x + threadIdx.x;
    if (i < N_NODES) g_deg[i] = 0;
    if (i < 2 * D) { g_musum2[i] = 0.f; g_varsum2[i] = 0.f; }
}
__global__ void k_count(const int* __restrict__ ei) {
    int i = blockIdx.x * blockDim.x + threadIdx.x;
    if (i >= ET) return;
    int dst = (i < N_EDGES) ? ei[N_EDGES + i] : (i - N_EDGES);
    atomicAdd(&g_deg[dst], 1);
}
__global__ void k_bsums() {
    int tid = threadIdx.x;
    int i = blockIdx.x * 256 + tid;
    int v = (i < N_NODES) ? g_deg[i] : 0;
    int lane = tid & 31, wid = tid >> 5;
#pragma unroll
    for (int o = 16; o; o >>= 1) v += __shfl_down_sync(0xffffffff, v, o);
    __shared__ int ws[8];
    if (lane == 0) ws[wid] = v;
    __syncthreads();
    if (tid == 0) {
        int s = 0;
#pragma unroll
        for (int w = 0; w < 8; w++) s += ws[w];
        g_bsum[blockIdx.x] = s;
    }
}
__global__ void k_scan2() {
    int tid = threadIdx.x;
    int lane = tid & 31, wid = tid >> 5;
    int v = (tid < NB_SCAN) ? g_bsum[tid] : 0;
    int x = v;
#pragma unroll
    for (int o = 1; o < 32; o <<= 1) {
        int t = __shfl_up_sync(0xffffffff, x, o);
        if (lane >= o) x += t;
    }
    __shared__ int ws[8];
    if (lane == 31) ws[wid] = x;
    __syncthreads();
    if (wid == 0 && lane < 8) {
        int y = ws[lane];
#pragma unroll
        for (int o = 1; o < 8; o <<= 1) {
            int t = __shfl_up_sync(0xff, y, o);
            if (lane >= o) y += t;
        }
        ws[lane] = y;
    }
    __syncthreads();
    int prefix = wid ? ws[wid - 1] : 0;
    if (tid < NB_SCAN) g_boff[tid] = prefix + x - v;
}
__global__ void k_addback() {
    int tid = threadIdx.x;
    int i = blockIdx.x * 256 + tid;
    int v = (i < N_NODES) ? g_deg[i] : 0;
    int lane = tid & 31, wid = tid >> 5;
    int x = v;
#pragma unroll
    for (int o = 1; o < 32; o <<= 1) {
        int t = __shfl_up_sync(0xffffffff, x, o);
        if (lane >= o) x += t;
    }
    __shared__ int ws[8];
    if (lane == 31) ws[wid] = x;
    __syncthreads();
    if (wid == 0 && lane < 8) {
        int y = ws[lane];
#pragma unroll
        for (int o = 1; o < 8; o <<= 1) {
            int t = __shfl_up_sync(0xff, y, o);
            if (lane >= o) y += t;
        }
        ws[lane] = y;
    }
    __syncthreads();
    int prefix = (wid ? ws[wid - 1] : 0) + g_boff[blockIdx.x];
    int excl = prefix + x - v;
    if (i < N_NODES) { g_off[i] = excl; g_cur[i] = excl; }
    if (i == 0) g_off[N_NODES] = ET;
}
__global__ void k_fill(const int* __restrict__ ei) {
    int i = blockIdx.x * blockDim.x + threadIdx.x;
    if (i >= ET) return;
    int src, dst;
    if (i < N_EDGES) { src = ei[i]; dst = ei[N_EDGES + i]; }
    else { src = dst = i - N_EDGES; }
    int pos = atomicAdd(&g_cur[dst], 1);
    g_srcl[pos] = src;
}

// ================= weight conversion =================
__global__ void k_cvt_w(const float* __restrict__ W) {
    int i = blockIdx.x * blockDim.x + threadIdx.x;
    if (i >= N_NODES * H3 / 4) return;
    float4 v = ((const float4*)W)[i];
    __nv_bfloat162 lo = __floats2bfloat162_rn(v.x, v.y);
    __nv_bfloat162 hi = __floats2bfloat162_rn(v.z, v.w);
    ((__nv_bfloat162*)g_w16)[i * 2] = lo;
    ((__nv_bfloat162*)g_w16)[i * 2 + 1] = hi;
}

// ================= cp.async helpers =================
__device__ __forceinline__ void cp_async16(uint32_t saddr, const void* gptr, int srcBytes) {
    asm volatile("cp.async.cg.shared.global [%0], [%1], 16, %2;\n"
                 :: "r"(saddr), "l"(gptr), "r"(srcBytes));
}
__device__ __forceinline__ void cp_commit() {
    asm volatile("cp.async.commit_group;\n");
}
template <int NW>
__device__ __forceinline__ void cp_wait() {
    asm volatile("cp.async.wait_group %0;\n" :: "n"(NW));
}

// ================= mma wrappers =================
__device__ __forceinline__ void mma_tf32(float c[4], uint32_t a0, uint32_t a1,
                                         uint32_t a2, uint32_t a3,
                                         uint32_t b0, uint32_t b1) {
    asm volatile(
        "mma.sync.aligned.m16n8k8.row.col.f32.tf32.tf32.f32 "
        "{%0,%1,%2,%3}, {%4,%5,%6,%7}, {%8,%9}, {%0,%1,%2,%3};"
        : "+f"(c[0]), "+f"(c[1]), "+f"(c[2]), "+f"(c[3])
        : "r"(a0), "r"(a1), "r"(a2), "r"(a3), "r"(b0), "r"(b1));
}
__device__ __forceinline__ void mma_bf16(float c[4], uint32_t a0, uint32_t a1,
                                         uint32_t a2, uint32_t a3,
                                         uint32_t b0, uint32_t b1) {
    asm volatile(
        "mma.sync.aligned.m16n8k16.row.col.f32.bf16.bf16.f32 "
        "{%0,%1,%2,%3}, {%4,%5,%6,%7}, {%8,%9}, {%0,%1,%2,%3};"
        : "+f"(c[0]), "+f"(c[1]), "+f"(c[2]), "+f"(c[3])
        : "r"(a0), "r"(a1), "r"(a2), "r"(a3), "r"(b0), "r"(b1));
}

// ================= bf16 tensor-core GEMM for lin2 (+ fused LSE partials) ===
#define BPAD 72
#define BSTAGE (128 * BPAD)
#define LIN2_SMEM_B (4 * BSTAGE * 2)
__global__ __launch_bounds__(256) void k_mma_lin2(
    const float* __restrict__ bias, float* __restrict__ out)
{
    extern __shared__ __nv_bfloat16 smem16[];
    const int K = H3, Nn = N_NODES;
    __nv_bfloat16* Abuf = smem16;
    __nv_bfloat16* Bbuf = smem16 + 2 * BSTAGE;

    int tid = threadIdx.x;
    int warp = tid >> 5, lane = tid & 31;
    int wm = (warp & 1) * 64;
    int wnw = warp >> 1;
    int wn = wnw * 32;
    int bm = blockIdx.y * 128;
    int bn = blockIdx.x * 128;

    float c[4][4][4];
#pragma unroll
    for (int mt = 0; mt < 4; mt++)
#pragma unroll
        for (int nt = 0; nt < 4; nt++)
#pragma unroll
            for (int r = 0; r < 4; r++) c[mt][nt][r] = 0.f;

    int gr = lane >> 2, gc = lane & 3;

    auto load_tile = [&](int it, int stage) {
        int k0 = it * 64;
        __nv_bfloat16* Ad = Abuf + stage * BSTAGE;
        __nv_bfloat16* Bd = Bbuf + stage * BSTAGE;
#pragma unroll
        for (int l = 0; l < 4; l++) {
            int linear = tid + l * 256;
            int row = linear >> 3;
            int kc = (linear & 7) * 8;
            uint32_t sa = (uint32_t)__cvta_generic_to_shared(Ad + row * BPAD + kc);
            cp_async16(sa, g_z16 + (size_t)(bm + row) * K + k0 + kc, 16);
            int grow = bn + row;
            int ok = (grow < Nn);
            uint32_t sb = (uint32_t)__cvta_generic_to_shared(Bd + row * BPAD + kc);
            cp_async16(sb, g_w16 + (size_t)(ok ? grow : 0) * K + k0 + kc, ok ? 16 : 0);
        }
        cp_commit();
    };

    const int NIT = K / 64;
    load_tile(0, 0);
    for (int it = 0; it < NIT; it++) {
        int cur = it & 1;
        if (it + 1 < NIT) { load_tile(it + 1, cur ^ 1); cp_wait<1>(); }
        else cp_wait<0>();
        __syncthreads();

        const __nv_bfloat16* Ac = Abuf + cur * BSTAGE;
        const __nv_bfloat16* Bc = Bbuf + cur * BSTAGE;
#pragma unroll
        for (int ks = 0; ks < 4; ks++) {
            int kb = ks * 16;
            uint32_t a[4][4];
#pragma unroll
            for (int mt = 0; mt < 4; mt++) {
                int mrow = wm + mt * 16 + gr;
                a[mt][0] = *(const uint32_t*)&Ac[mrow * BPAD + kb + gc * 2];
                a[mt][1] = *(const uint32_t*)&Ac[(mrow + 8) * BPAD + kb + gc * 2];
                a[mt][2] = *(const uint32_t*)&Ac[mrow * BPAD + kb + 8 + gc * 2];
                a[mt][3] = *(const uint32_t*)&Ac[(mrow + 8) * BPAD + kb + 8 + gc * 2];
            }
            uint32_t b[4][2];
#pragma unroll
            for (int nt = 0; nt < 4; nt++) {
                int ncol = wn + nt * 8 + gr;
                b[nt][0] = *(const uint32_t*)&Bc[ncol * BPAD + kb + gc * 2];
                b[nt][1] = *(const uint32_t*)&Bc[ncol * BPAD + kb + 8 + gc * 2];
            }
#pragma unroll
            for (int mt = 0; mt < 4; mt++)
#pragma unroll
                for (int nt = 0; nt < 4; nt++)
                    mma_bf16(c[mt][nt], a[mt][0], a[mt][1], a[mt][2], a[mt][3],
                             b[nt][0], b[nt][1]);
        }
        __syncthreads();
    }

    float* smf   = (float*)smem16;
    float* sm_pm  = smf;
    float* sm_max = smf + 512;
    float* sm_ps  = smf + 512 + 128;

    int crow = lane >> 2, ccol = (lane & 3) * 2;
    float bv[4][2];
    bool ok[4][2];
#pragma unroll
    for (int nt = 0; nt < 4; nt++)
#pragma unroll
        for (int j = 0; j < 2; j++) {
            int col = bn + wn + nt * 8 + ccol + j;
            ok[nt][j] = (col < Nn);
            bv[nt][j] = ok[nt][j] ? bias[col] : 0.f;
        }

#pragma unroll
    for (int mt = 0; mt < 4; mt++) {
#pragma unroll
        for (int h = 0; h < 2; h++) {
            int lrow = wm + mt * 16 + crow + h * 8;
            int row = bm + lrow;
            float vmax = NEG_INF;
#pragma unroll
            for (int nt = 0; nt < 4; nt++)
#pragma unroll
                for (int j = 0; j < 2; j++) {
                    if (ok[nt][j]) {
                        float v = c[mt][nt][h * 2 + j] + bv[nt][j];
                        out[(size_t)row * Nn + (bn + wn + nt * 8 + ccol + j)] = v;
                        vmax = fmaxf(vmax, v);
                    }
                }
            vmax = fmaxf(vmax, __shfl_xor_sync(0xffffffff, vmax, 1));
            vmax = fmaxf(vmax, __shfl_xor_sync(0xffffffff, vmax, 2));
            if ((lane & 3) == 0) sm_pm[lrow * 4 + wnw] = vmax;
        }
    }
    __syncthreads();
    if (tid < 128) {
        float m = fmaxf(fmaxf(sm_pm[tid * 4], sm_pm[tid * 4 + 1]),
                        fmaxf(sm_pm[tid * 4 + 2], sm_pm[tid * 4 + 3]));
        sm_max[tid] = m;
    }
    __syncthreads();
#pragma unroll
    for (int mt = 0; mt < 4; mt++) {
#pragma unroll
        for (int h = 0; h < 2; h++) {
            int lrow = wm + mt * 16 + crow + h * 8;
            float M = sm_max[lrow];
            float ls = 0.f;
#pragma unroll
            for (int nt = 0; nt < 4; nt++)
#pragma unroll
                for (int j = 0; j < 2; j++)
                    if (ok[nt][j])
                        ls += __expf(c[mt][nt][h * 2 + j] + bv[nt][j] - M);
            ls += __shfl_xor_sync(0xffffffff, ls, 1);
            ls += __shfl_xor_sync(0xffffffff, ls, 2);
            if ((lane & 3) == 0) sm_ps[lrow * 4 + wnw] = ls;
        }
    }
    __syncthreads();
    if (tid < 128) {
        float s = sm_ps[tid * 4] + sm_ps[tid * 4 + 1] +
                  sm_ps[tid * 4 + 2] + sm_ps[tid * 4 + 3];
        g_pmax[(size_t)(bm + tid) * NT_TILES + blockIdx.x] = sm_max[tid];
        g_psum[(size_t)(bm + tid) * NT_TILES + blockIdx.x] = s;
    }
}

// ================= tf32 feature GEMM with fused attention dots =================
#define MMA_PAD 36
#define MMA_STAGE_F (128 * MMA_PAD)
#define FEAT_SMEM_B (4 * MMA_STAGE_F * 4)
__global__ __launch_bounds__(256) void k_mma_feat(
    const float* __restrict__ Aext, const float* __restrict__ W,
    const float* __restrict__ asrc, const float* __restrict__ adst, int asel)
{
    extern __shared__ float smemf[];
    const float* A = asel ? g_hn : Aext;
    const int M = N_NODES, K = D;
    float* Abuf = smemf;
    float* Bbuf = smemf + 2 * MMA_STAGE_F;

    int tid = threadIdx.x;
    int warp = tid >> 5, lane = tid & 31;
    int wm = (warp & 1) * 64;
    int wnw = warp >> 1;
    int wn = wnw * 32;
    int bm = blockIdx.y * 128;

    float c[4][4][4];
#pragma unroll
    for (int mt = 0; mt < 4; mt++)
#pragma unroll
        for (int nt = 0; nt < 4; nt++)
#pragma unroll
            for (int r = 0; r < 4; r++) c[mt][nt][r] = 0.f;

    int gr = lane >> 2, gc = lane & 3;

    auto load_tile = [&](int it, int stage) {
        int k0 = it * 32;
        float* Ad = Abuf + stage * MMA_STAGE_F;
        float* Bd = Bbuf + stage * MMA_STAGE_F;
#pragma unroll
        for (int l = 0; l < 4; l++) {
            int linear = tid + l * 256;
            int row = linear >> 3;
            int kc = (linear & 7) * 4;
            int ar = bm + row;
            int okA = (ar < M);
            uint32_t sa = (uint32_t)__cvta_generic_to_shared(Ad + row * MMA_PAD + kc);
            cp_async16(sa, A + (size_t)(okA ? ar : 0) * K + k0 + kc, okA ? 16 : 0);
            uint32_t sb = (uint32_t)__cvta_generic_to_shared(Bd + row * MMA_PAD + kc);
            cp_async16(sb, W + (size_t)row * K + k0 + kc, 16);
        }
        cp_commit();
    };

    const int NIT = K / 32;
    load_tile(0, 0);
    for (int it = 0; it < NIT; it++) {
        int cur = it & 1;
        if (it + 1 < NIT) { load_tile(it + 1, cur ^ 1); cp_wait<1>(); }
        else cp_wait<0>();
        __syncthreads();

        const float* Ac = Abuf + cur * MMA_STAGE_F;
        const float* Bc = Bbuf + cur * MMA_STAGE_F;
#pragma unroll
        for (int ks = 0; ks < 4; ks++) {
            int kb = ks * 8;
            uint32_t a[4][4];
#pragma unroll
            for (int mt = 0; mt < 4; mt++) {
                int mrow = wm + mt * 16 + gr;
                a[mt][0] = __float_as_uint(Ac[mrow * MMA_PAD + kb + gc]);
                a[mt][1] = __float_as_uint(Ac[(mrow + 8) * MMA_PAD + kb + gc]);
                a[mt][2] = __float_as_uint(Ac[mrow * MMA_PAD + kb + gc + 4]);
                a[mt][3] = __float_as_uint(Ac[(mrow + 8) * MMA_PAD + kb + gc + 4]);
            }
            uint32_t b[4][2];
#pragma unroll
            for (int nt = 0; nt < 4; nt++) {
                int ncol = wn + nt * 8 + gr;
                b[nt][0] = __float_as_uint(Bc[ncol * MMA_PAD + kb + gc]);
                b[nt][1] = __float_as_uint(Bc[ncol * MMA_PAD + kb + gc + 4]);
            }
#pragma unroll
            for (int mt = 0; mt < 4; mt++)
#pragma unroll
                for (int nt = 0; nt < 4; nt++)
                    mma_tf32(c[mt][nt], a[mt][0], a[mt][1], a[mt][2], a[mt][3],
                             b[nt][0], b[nt][1]);
        }
        __syncthreads();
    }

    // epilogue: store g_h + fused attention dot partials
    float* sm_as = smemf;          // [128][4]
    float* sm_ad = smemf + 512;    // [128][4]

    int crow = lane >> 2, ccol = (lane & 3) * 2;
    float av[4][2], dv[4][2];
#pragma unroll
    for (int nt = 0; nt < 4; nt++)
#pragma unroll
        for (int j = 0; j < 2; j++) {
            int col = wn + nt * 8 + ccol + j;
            av[nt][j] = asrc[col];
            dv[nt][j] = adst[col];
        }

#pragma unroll
    for (int mt = 0; mt < 4; mt++) {
#pragma unroll
        for (int h = 0; h < 2; h++) {
            int lrow = wm + mt * 16 + crow + h * 8;
            int row = bm + lrow;
            float pas = 0.f, pad = 0.f;
            if (row < M) {
#pragma unroll
                for (int nt = 0; nt < 4; nt++) {
#pragma unroll
                    for (int j = 0; j < 2; j++) {
                        float v = c[mt][nt][h * 2 + j];
                        g_h[(size_t)row * D + (wn + nt * 8 + ccol + j)] = v;
                        pas += v * av[nt][j];
                        pad += v * dv[nt][j];
                    }
                }
            }
            pas += __shfl_xor_sync(0xffffffff, pas, 1);
            pas += __shfl_xor_sync(0xffffffff, pas, 2);
            pad += __shfl_xor_sync(0xffffffff, pad, 1);
            pad += __shfl_xor_sync(0xffffffff, pad, 2);
            if ((lane & 3) == 0) {
                sm_as[lrow * 4 + wnw] = pas;
                sm_ad[lrow * 4 + wnw] = pad;
            }
        }
    }
    __syncthreads();
    if (tid < 128) {
        int row = bm + tid;
        if (row < M) {
            g_as[row] = sm_as[tid * 4] + sm_as[tid * 4 + 1] +
                        sm_as[tid * 4 + 2] + sm_as[tid * 4 + 3];
            g_ad[row] = sm_ad[tid * 4] + sm_ad[tid * 4 + 1] +
                        sm_ad[tid * 4 + 2] + sm_ad[tid * 4 + 3];
        }
    }
}

// ================= fp32 SGEMM lin1 with fused gather =================
__global__ __launch_bounds__(256) void k_sgemm_lin1(
    const int* __restrict__ x, const float* __restrict__ Bm,
    const float* __restrict__ bias)
{
    const int Nn = H3, K = H3;
    float* C = g_z1;

    __shared__ float As[8][128];
    __shared__ float Bs[8][128];

    int tid = threadIdx.x;
    int tx = tid & 15, ty = tid >> 4;
    int bm = blockIdx.y * 128, bn = blockIdx.x * 128;

    float acc[8][8];
#pragma unroll
    for (int i = 0; i < 8; i++)
#pragma unroll
        for (int j = 0; j < 8; j++) acc[i][j] = 0.f;

    int lr = tid >> 1;
    int lk = (tid & 1) * 4;

    for (int k0 = 0; k0 < K; k0 += 8) {
        int ar = bm + lr;                         // 0..1023, always valid
        int kidx = k0 + lk;
        int node = x[ar * 3 + (kidx >> 7)];
        float4 a4 = *(const float4*)(g_hn + (size_t)node * D + (kidx & 127));
        As[lk + 0][lr] = a4.x; As[lk + 1][lr] = a4.y;
        As[lk + 2][lr] = a4.z; As[lk + 3][lr] = a4.w;

        float4 b4 = make_float4(0.f, 0.f, 0.f, 0.f);
        int br = bn + lr;
        if (br < Nn) b4 = *(const float4*)(Bm + (size_t)br * K + kidx);
        Bs[lk + 0][lr] = b4.x; Bs[lk + 1][lr] = b4.y;
        Bs[lk + 2][lr] = b4.z; Bs[lk + 3][lr] = b4.w;
        __syncthreads();

#pragma unroll
        for (int k = 0; k < 8; k++) {
            float4 a0 = *(const float4*)&As[k][ty * 8];
            float4 a1 = *(const float4*)&As[k][ty * 8 + 4];
            float4 b0 = *(const float4*)&Bs[k][tx * 8];
            float4 b1 = *(const float4*)&Bs[k][tx * 8 + 4];
            float a[8] = {a0.x, a0.y, a0.z, a0.w, a1.x, a1.y, a1.z, a1.w};
            float b[8] = {b0.x, b0.y, b0.z, b0.w, b1.x, b1.y, b1.z, b1.w};
#pragma unroll
            for (int i = 0; i < 8; i++)
#pragma unroll
                for (int j = 0; j < 8; j++) acc[i][j] += a[i] * b[j];
        }
        __syncthreads();
    }

#pragma unroll
    for (int i = 0; i < 8; i++) {
        int row = bm + ty * 8 + i;
#pragma unroll
        for (int j = 0; j < 8; j++) {
            int col = bn + tx * 8 + j;
            if (col < Nn) C[(size_t)row * Nn + col] = acc[i][j] + bias[col];
        }
    }
}

// ================= LSE merge + subtract =================
__global__ void k_reduce_lse() {
    int row = blockIdx.x * 8 + (threadIdx.x >> 5);
    int lane = threadIdx.x & 31;
    const float* pm = g_pmax + (size_t)row * NT_TILES;
    const float* ps = g_psum + (size_t)row * NT_TILES;
    float M = NEG_INF;
    for (int i = lane; i < NT_TILES; i += 32) M = fmaxf(M, pm[i]);
#pragma unroll
    for (int o = 16; o; o >>= 1) M = fmaxf(M, __shfl_xor_sync(0xffffffff, M, o));
    float S = 0.f;
    for (int i = lane; i < NT_TILES; i += 32) S += ps[i] * __expf(pm[i] - M);
#pragma unroll
    for (int o = 16; o; o >>= 1) S += __shfl_xor_sync(0xffffffff, S, o);
    if (lane == 0) g_lse[row] = M + logf(S);
}

__global__ void k_sub_lse(float* __restrict__ out) {
    int idx = blockIdx.x * blockDim.x + threadIdx.x;
    if (idx >= BQ * 12500) return;
    int row = idx / 12500;
    float l = g_lse[row];
    float4* p = (float4*)out + idx;
    float4 v = *p;
    v.x -= l; v.y -= l; v.z -= l; v.w -= l;
    *p = v;
}

// ================= per-node attention aggregate =================
__global__ void k_node_attagg() {
    int gt = blockIdx.x * blockDim.x + threadIdx.x;
    int node = gt >> 5, lane = gt & 31;
    if (node >= N_NODES) return;
    int beg = g_off[node], end = g_off[node + 1];
    float ad = g_ad[node];

    float m = NEG_INF;
    for (int i = beg + lane; i < end; i += 32) {
        float s = g_as[g_srcl[i]] + ad;
        float e = (s > 0.f) ? s : 0.2f * s;
        g_e[i] = e;
        m = fmaxf(m, e);
    }
#pragma unroll
    for (int o = 16; o; o >>= 1) m = fmaxf(m, __shfl_xor_sync(0xffffffff, m, o));

    __syncwarp();
    float den = 0.f;
    for (int i = beg + lane; i < end; i += 32) {
        float ex = __expf(g_e[i] - m);
        g_e[i] = ex;
        den += ex;
    }
#pragma unroll
    for (int o = 16; o; o >>= 1) den += __shfl_xor_sync(0xffffffff, den, o);
    float inv = 1.f / den;
    __syncwarp();

    float4 acc = make_float4(0.f, 0.f, 0.f, 0.f);
    int i = beg;
    for (; i + 1 < end; i += 2) {
        float w0 = g_e[i] * inv, w1 = g_e[i + 1] * inv;
        int s0 = g_srcl[i], s1 = g_srcl[i + 1];
        float4 h0 = *(const float4*)(g_h + (size_t)s0 * D + lane * 4);
        float4 h1 = *(const float4*)(g_h + (size_t)s1 * D + lane * 4);
        acc.x += w0 * h0.x + w1 * h1.x;
        acc.y += w0 * h0.y + w1 * h1.y;
        acc.z += w0 * h0.z + w1 * h1.z;
        acc.w += w0 * h0.w + w1 * h1.w;
    }
    if (i < end) {
        float w = g_e[i] * inv;
        int s = g_srcl[i];
        float4 hv = *(const float4*)(g_h + (size_t)s * D + lane * 4);
        acc.x += w * hv.x; acc.y += w * hv.y;
        acc.z += w * hv.z; acc.w += w * hv.w;
    }
    *(float4*)(g_agg + (size_t)node * D + lane * 4) = acc;
}

// ================= GraphNorm =================
#define RPB 64
__global__ void k_colstats(int layer) {
    int col = threadIdx.x;
    int r0 = blockIdx.x * RPB;
    int r1 = min(r0 + RPB, N_NODES);
    float s = 0.f, s2 = 0.f;
    for (int r = r0; r < r1; r++) {
        float a = g_agg[(size_t)r * D + col];
        s += a; s2 += a * a;
    }
    atomicAdd(&g_musum2[layer * D + col], s);
    atomicAdd(&g_varsum2[layer * D + col], s2);
}
__global__ void k_normalize(const float* __restrict__ bb, const float* __restrict__ gw,
                            const float* __restrict__ gb, const float* __restrict__ ms,
                            int layer) {
    int idx = blockIdx.x * blockDim.x + threadIdx.x;
    if (idx >= N_NODES * D) return;
    int d = idx & (D - 1);
    float S1 = g_musum2[layer * D + d] * (1.f / N_NODES);
    float S2 = g_varsum2[layer * D + d] * (1.f / N_NODES);
    float bv = bb[d];
    float mu = S1 + bv;
    float cc = bv - mu * ms[d];
    float var = S2 + 2.f * cc * S1 + cc * cc;
    float istd = rsqrtf(var + EPSV);
    float t = g_agg[idx] + cc;
    float v = t * istd * gw[d] + gb[d];
    g_hn[idx] = v > 0.f ? v : 0.f;
}

// ================= head BN =================
__global__ void k_bn_relu(const float* __restrict__ bw, const float* __restrict__ bb) {
    int c = blockIdx.x;
    int t = threadIdx.x;
    __shared__ float sm[256], ss[256];
    float s = 0.f, s2 = 0.f;
    for (int r = t; r < BQ; r += 256) {
        float v = g_z1[r * H3 + c];
        s += v; s2 += v * v;
    }
    sm[t] = s; ss[t] = s2;
    __syncthreads();
    for (int o = 128; o; o >>= 1) {
        if (t < o) { sm[t] += sm[t + o]; ss[t] += ss[t + o]; }
        __syncthreads();
    }
    float mu = sm[0] * (1.f / BQ);
    float var = ss[0] * (1.f / BQ) - mu * mu;
    float istd = rsqrtf(var + EPSV);
    float w = bw[c], bias = bb[c];
    for (int r = t; r < BQ; r += 256) {
        float v = (g_z1[r * H3 + c] - mu) * istd * w + bias;
        g_z16[r * H3 + c] = __float2bfloat16(v > 0.f ? v : 0.f);
    }
}

// ================= host driver =================
extern "C" void kernel_launch(void* const* d_in, const int* in_sizes, int n_in,
                              void* d_out, int out_size)
{
    const int*   x       = (const int*)  d_in[0];
    const int*   ei      = (const int*)  d_in[1];
    const float* emb     = (const float*)d_in[2];
    const float* W1      = (const float*)d_in[3];
    const float* asrc1   = (const float*)d_in[4];
    const float* adst1   = (const float*)d_in[5];
    const float* b1      = (const float*)d_in[6];
    const float* gn1w    = (const float*)d_in[7];
    const float* gn1b    = (const float*)d_in[8];
    const float* gn1ms   = (const float*)d_in[9];
    const float* W2      = (const float*)d_in[10];
    const float* asrc2   = (const float*)d_in[11];
    const float* adst2   = (const float*)d_in[12];
    const float* b2      = (const float*)d_in[13];
    const float* gn2w    = (const float*)d_in[14];
    const float* gn2b    = (const float*)d_in[15];
    const float* gn2ms   = (const float*)d_in[16];
    const float* lin1W   = (const float*)d_in[17];
    const float* lin1b   = (const float*)d_in[18];
    const float* bnw     = (const float*)d_in[19];
    const float* bnb     = (const float*)d_in[20];
    const float* lin2W   = (const float*)d_in[21];
    const float* lin2b   = (const float*)d_in[22];
    float* out = (float*)d_out;

    cudaFuncSetAttribute(k_mma_lin2, cudaFuncAttributeMaxDynamicSharedMemorySize, LIN2_SMEM_B);
    cudaFuncSetAttribute(k_mma_feat, cudaFuncAttributeMaxDynamicSharedMemorySize, FEAT_SMEM_B);

    dim3 gf(1, NT_TILES);

    // launches 1-5 (prep); launch 6 = k_mma_feat layer1 (ncu -s 5 -c 1 target)
    k_cvt_w<<<(N_NODES * H3 / 4 + 255) / 256, 256>>>(lin2W);          // 1
    k_zero_deg<<<(N_NODES + 255) / 256, 256>>>();                     // 2
    k_count<<<(ET + 255) / 256, 256>>>(ei);                           // 3
    k_bsums<<<NB_SCAN, 256>>>();                                      // 4
    k_scan2<<<1, 256>>>();                                            // 5
    k_mma_feat<<<gf, 256, FEAT_SMEM_B>>>(emb, W1, asrc1, adst1, 0);   // 6
    k_addback<<<NB_SCAN, 256>>>();                                    // 7
    k_fill<<<(ET + 255) / 256, 256>>>(ei);                            // 8

    // --- layer 1 rest ---
    k_node_attagg<<<(N_NODES * 32 + 255) / 256, 256>>>();
    k_colstats<<<(N_NODES + RPB - 1) / RPB, D>>>(0);
    k_normalize<<<(N_NODES * D + 255) / 256, 256>>>(b1, gn1w, gn1b, gn1ms, 0);

    // --- layer 2 ---
    k_mma_feat<<<gf, 256, FEAT_SMEM_B>>>(nullptr, W2, asrc2, adst2, 1);
    k_node_attagg<<<(N_NODES * 32 + 255) / 256, 256>>>();
    k_colstats<<<(N_NODES + RPB - 1) / RPB, D>>>(1);
    k_normalize<<<(N_NODES * D + 255) / 256, 256>>>(b2, gn2w, gn2b, gn2ms, 1);

    // --- head ---
    dim3 gz1((H3 + 127) / 128, BQ / 128);
    k_sgemm_lin1<<<gz1, 256>>>(x, lin1W, lin1b);
    k_bn_relu<<<H3, 256>>>(bnw, bnb);
    dim3 gz2(NT_TILES, BQ / 128);
    k_mma_lin2<<<gz2, 256, LIN2_SMEM_B>>>(lin2b, out);
    k_reduce_lse<<<BQ / 8, 256>>>();
    k_sub_lse<<<(BQ * 12500 + 255) / 256, 256>>>(out);
}

// round 8
// speedup vs baseline: 3.9350x; 1.0388x over previous
#include <cuda_runtime.h>
#include <cuda_bf16.h>
#include <math.h>
#include <stdint.h>

#define N_NODES 50000
#define N_EDGES 800000
#define ET (N_EDGES + N_NODES)
#define D 128
#define BQ 1024
#define H3 384
#define EPSV 1e-5f
#define NT_TILES 391             // ceil(50000/128)
#define NB_SCAN 196              // ceil(50000/256)

#define NEG_INF (__int_as_float(0xff800000))

// ---------------- scratch (device globals; no allocation) ----------------
__device__ __nv_bfloat16 g_h16[(size_t)N_NODES * D];   // bf16 transformed features
__device__ float g_agg[N_NODES * D];
__device__ float g_hn[N_NODES * D];
__device__ float g_as[N_NODES];
__device__ float g_ad[N_NODES];
__device__ float g_e[ET];
__device__ float g_musum2[2 * D];
__device__ float g_varsum2[2 * D];
__device__ float g_z1[BQ * H3];
__device__ float g_lse[BQ];
__device__ float g_pmax[(size_t)BQ * NT_TILES];
__device__ float g_psum[(size_t)BQ * NT_TILES];
__device__ __nv_bfloat16 g_w16[(size_t)N_NODES * H3];
__device__ __nv_bfloat16 g_z16[BQ * H3];
// CSR
__device__ int g_deg[N_NODES];
__device__ int g_off[N_NODES + 1];
__device__ int g_cur[N_NODES];
__device__ int g_srcl[ET];
__device__ int g_bsum[NB_SCAN];
__device__ int g_boff[NB_SCAN];

// ================= CSR build =================
__global__ void k_zero_deg() {
    int i = blockIdx.x * blockDim.x + threadIdx.x;
    if (i < N_NODES) g_deg[i] = 0;
    if (i < 2 * D) { g_musum2[i] = 0.f; g_varsum2[i] = 0.f; }
}
__global__ void k_count(const int* __restrict__ ei) {
    int i = blockIdx.x * blockDim.x + threadIdx.x;
    if (i >= ET) return;
    int dst = (i < N_EDGES) ? ei[N_EDGES + i] : (i - N_EDGES);
    atomicAdd(&g_deg[dst], 1);
}
__global__ void k_bsums() {
    int tid = threadIdx.x;
    int i = blockIdx.x * 256 + tid;
    int v = (i < N_NODES) ? g_deg[i] : 0;
    int lane = tid & 31, wid = tid >> 5;
#pragma unroll
    for (int o = 16; o; o >>= 1) v += __shfl_down_sync(0xffffffff, v, o);
    __shared__ int ws[8];
    if (lane == 0) ws[wid] = v;
    __syncthreads();
    if (tid == 0) {
        int s = 0;
#pragma unroll
        for (int w = 0; w < 8; w++) s += ws[w];
        g_bsum[blockIdx.x] = s;
    }
}
__global__ void k_scan2() {
    int tid = threadIdx.x;
    int lane = tid & 31, wid = tid >> 5;
    int v = (tid < NB_SCAN) ? g_bsum[tid] : 0;
    int x = v;
#pragma unroll
    for (int o = 1; o < 32; o <<= 1) {
        int t = __shfl_up_sync(0xffffffff, x, o);
        if (lane >= o) x += t;
    }
    __shared__ int ws[8];
    if (lane == 31) ws[wid] = x;
    __syncthreads();
    if (wid == 0 && lane < 8) {
        int y = ws[lane];
#pragma unroll
        for (int o = 1; o < 8; o <<= 1) {
            int t = __shfl_up_sync(0xff, y, o);
            if (lane >= o) y += t;
        }
        ws[lane] = y;
    }
    __syncthreads();
    int prefix = wid ? ws[wid - 1] : 0;
    if (tid < NB_SCAN) g_boff[tid] = prefix + x - v;
}
__global__ void k_addback() {
    int tid = threadIdx.x;
    int i = blockIdx.x * 256 + tid;
    int v = (i < N_NODES) ? g_deg[i] : 0;
    int lane = tid & 31, wid = tid >> 5;
    int x = v;
#pragma unroll
    for (int o = 1; o < 32; o <<= 1) {
        int t = __shfl_up_sync(0xffffffff, x, o);
        if (lane >= o) x += t;
    }
    __shared__ int ws[8];
    if (lane == 31) ws[wid] = x;
    __syncthreads();
    if (wid == 0 && lane < 8) {
        int y = ws[lane];
#pragma unroll
        for (int o = 1; o < 8; o <<= 1) {
            int t = __shfl_up_sync(0xff, y, o);
            if (lane >= o) y += t;
        }
        ws[lane] = y;
    }
    __syncthreads();
    int prefix = (wid ? ws[wid - 1] : 0) + g_boff[blockIdx.x];
    int excl = prefix + x - v;
    if (i < N_NODES) { g_off[i] = excl; g_cur[i] = excl; }
    if (i == 0) g_off[N_NODES] = ET;
}
__global__ void k_fill(const int* __restrict__ ei) {
    int i = blockIdx.x * blockDim.x + threadIdx.x;
    if (i >= ET) return;
    int src, dst;
    if (i < N_EDGES) { src = ei[i]; dst = ei[N_EDGES + i]; }
    else { src = dst = i - N_EDGES; }
    int pos = atomicAdd(&g_cur[dst], 1);
    g_srcl[pos] = src;
}

// ================= weight conversion =================
__global__ void k_cvt_w(const float* __restrict__ W) {
    int i = blockIdx.x * blockDim.x + threadIdx.x;
    if (i >= N_NODES * H3 / 4) return;
    float4 v = ((const float4*)W)[i];
    __nv_bfloat162 lo = __floats2bfloat162_rn(v.x, v.y);
    __nv_bfloat162 hi = __floats2bfloat162_rn(v.z, v.w);
    ((__nv_bfloat162*)g_w16)[i * 2] = lo;
    ((__nv_bfloat162*)g_w16)[i * 2 + 1] = hi;
}

// ================= cp.async helpers =================
__device__ __forceinline__ void cp_async16(uint32_t saddr, const void* gptr, int srcBytes) {
    asm volatile("cp.async.cg.shared.global [%0], [%1], 16, %2;\n"
                 :: "r"(saddr), "l"(gptr), "r"(srcBytes));
}
__device__ __forceinline__ void cp_commit() {
    asm volatile("cp.async.commit_group;\n");
}
template <int NW>
__device__ __forceinline__ void cp_wait() {
    asm volatile("cp.async.wait_group %0;\n" :: "n"(NW));
}

// ================= mma wrappers =================
__device__ __forceinline__ void mma_tf32(float c[4], uint32_t a0, uint32_t a1,
                                         uint32_t a2, uint32_t a3,
                                         uint32_t b0, uint32_t b1) {
    asm volatile(
        "mma.sync.aligned.m16n8k8.row.col.f32.tf32.tf32.f32 "
        "{%0,%1,%2,%3}, {%4,%5,%6,%7}, {%8,%9}, {%0,%1,%2,%3};"
        : "+f"(c[0]), "+f"(c[1]), "+f"(c[2]), "+f"(c[3])
        : "r"(a0), "r"(a1), "r"(a2), "r"(a3), "r"(b0), "r"(b1));
}
__device__ __forceinline__ void mma_bf16(float c[4], uint32_t a0, uint32_t a1,
                                         uint32_t a2, uint32_t a3,
                                         uint32_t b0, uint32_t b1) {
    asm volatile(
        "mma.sync.aligned.m16n8k16.row.col.f32.bf16.bf16.f32 "
        "{%0,%1,%2,%3}, {%4,%5,%6,%7}, {%8,%9}, {%0,%1,%2,%3};"
        : "+f"(c[0]), "+f"(c[1]), "+f"(c[2]), "+f"(c[3])
        : "r"(a0), "r"(a1), "r"(a2), "r"(a3), "r"(b0), "r"(b1));
}

// ================= bf16 tensor-core GEMM for lin2 (+ fused LSE partials) ===
#define BPAD 72
#define BSTAGE (128 * BPAD)
#define LIN2_SMEM_B (4 * BSTAGE * 2)
__global__ __launch_bounds__(256) void k_mma_lin2(
    const float* __restrict__ bias, float* __restrict__ out)
{
    extern __shared__ __nv_bfloat16 smem16[];
    const int K = H3, Nn = N_NODES;
    __nv_bfloat16* Abuf = smem16;
    __nv_bfloat16* Bbuf = smem16 + 2 * BSTAGE;

    int tid = threadIdx.x;
    int warp = tid >> 5, lane = tid & 31;
    int wm = (warp & 1) * 64;
    int wnw = warp >> 1;
    int wn = wnw * 32;
    int bm = blockIdx.y * 128;
    int bn = blockIdx.x * 128;

    float c[4][4][4];
#pragma unroll
    for (int mt = 0; mt < 4; mt++)
#pragma unroll
        for (int nt = 0; nt < 4; nt++)
#pragma unroll
            for (int r = 0; r < 4; r++) c[mt][nt][r] = 0.f;

    int gr = lane >> 2, gc = lane & 3;

    auto load_tile = [&](int it, int stage) {
        int k0 = it * 64;
        __nv_bfloat16* Ad = Abuf + stage * BSTAGE;
        __nv_bfloat16* Bd = Bbuf + stage * BSTAGE;
#pragma unroll
        for (int l = 0; l < 4; l++) {
            int linear = tid + l * 256;
            int row = linear >> 3;
            int kc = (linear & 7) * 8;
            uint32_t sa = (uint32_t)__cvta_generic_to_shared(Ad + row * BPAD + kc);
            cp_async16(sa, g_z16 + (size_t)(bm + row) * K + k0 + kc, 16);
            int grow = bn + row;
            int ok = (grow < Nn);
            uint32_t sb = (uint32_t)__cvta_generic_to_shared(Bd + row * BPAD + kc);
            cp_async16(sb, g_w16 + (size_t)(ok ? grow : 0) * K + k0 + kc, ok ? 16 : 0);
        }
        cp_commit();
    };

    const int NIT = K / 64;
    load_tile(0, 0);
    for (int it = 0; it < NIT; it++) {
        int cur = it & 1;
        if (it + 1 < NIT) { load_tile(it + 1, cur ^ 1); cp_wait<1>(); }
        else cp_wait<0>();
        __syncthreads();

        const __nv_bfloat16* Ac = Abuf + cur * BSTAGE;
        const __nv_bfloat16* Bc = Bbuf + cur * BSTAGE;
#pragma unroll
        for (int ks = 0; ks < 4; ks++) {
            int kb = ks * 16;
            uint32_t a[4][4];
#pragma unroll
            for (int mt = 0; mt < 4; mt++) {
                int mrow = wm + mt * 16 + gr;
                a[mt][0] = *(const uint32_t*)&Ac[mrow * BPAD + kb + gc * 2];
                a[mt][1] = *(const uint32_t*)&Ac[(mrow + 8) * BPAD + kb + gc * 2];
                a[mt][2] = *(const uint32_t*)&Ac[mrow * BPAD + kb + 8 + gc * 2];
                a[mt][3] = *(const uint32_t*)&Ac[(mrow + 8) * BPAD + kb + 8 + gc * 2];
            }
            uint32_t b[4][2];
#pragma unroll
            for (int nt = 0; nt < 4; nt++) {
                int ncol = wn + nt * 8 + gr;
                b[nt][0] = *(const uint32_t*)&Bc[ncol * BPAD + kb + gc * 2];
                b[nt][1] = *(const uint32_t*)&Bc[ncol * BPAD + kb + 8 + gc * 2];
            }
#pragma unroll
            for (int mt = 0; mt < 4; mt++)
#pragma unroll
                for (int nt = 0; nt < 4; nt++)
                    mma_bf16(c[mt][nt], a[mt][0], a[mt][1], a[mt][2], a[mt][3],
                             b[nt][0], b[nt][1]);
        }
        __syncthreads();
    }

    float* smf   = (float*)smem16;
    float* sm_pm  = smf;
    float* sm_max = smf + 512;
    float* sm_ps  = smf + 512 + 128;

    int crow = lane >> 2, ccol = (lane & 3) * 2;
    float bv[4][2];
    bool ok[4][2];
#pragma unroll
    for (int nt = 0; nt < 4; nt++)
#pragma unroll
        for (int j = 0; j < 2; j++) {
            int col = bn + wn + nt * 8 + ccol + j;
            ok[nt][j] = (col < Nn);
            bv[nt][j] = ok[nt][j] ? bias[col] : 0.f;
        }

#pragma unroll
    for (int mt = 0; mt < 4; mt++) {
#pragma unroll
        for (int h = 0; h < 2; h++) {
            int lrow = wm + mt * 16 + crow + h * 8;
            int row = bm + lrow;
            float vmax = NEG_INF;
#pragma unroll
            for (int nt = 0; nt < 4; nt++)
#pragma unroll
                for (int j = 0; j < 2; j++) {
                    if (ok[nt][j]) {
                        float v = c[mt][nt][h * 2 + j] + bv[nt][j];
                        out[(size_t)row * Nn + (bn + wn + nt * 8 + ccol + j)] = v;
                        vmax = fmaxf(vmax, v);
                    }
                }
            vmax = fmaxf(vmax, __shfl_xor_sync(0xffffffff, vmax, 1));
            vmax = fmaxf(vmax, __shfl_xor_sync(0xffffffff, vmax, 2));
            if ((lane & 3) == 0) sm_pm[lrow * 4 + wnw] = vmax;
        }
    }
    __syncthreads();
    if (tid < 128) {
        float m = fmaxf(fmaxf(sm_pm[tid * 4], sm_pm[tid * 4 + 1]),
                        fmaxf(sm_pm[tid * 4 + 2], sm_pm[tid * 4 + 3]));
        sm_max[tid] = m;
    }
    __syncthreads();
#pragma unroll
    for (int mt = 0; mt < 4; mt++) {
#pragma unroll
        for (int h = 0; h < 2; h++) {
            int lrow = wm + mt * 16 + crow + h * 8;
            float M = sm_max[lrow];
            float ls = 0.f;
#pragma unroll
            for (int nt = 0; nt < 4; nt++)
#pragma unroll
                for (int j = 0; j < 2; j++)
                    if (ok[nt][j])
                        ls += __expf(c[mt][nt][h * 2 + j] + bv[nt][j] - M);
            ls += __shfl_xor_sync(0xffffffff, ls, 1);
            ls += __shfl_xor_sync(0xffffffff, ls, 2);
            if ((lane & 3) == 0) sm_ps[lrow * 4 + wnw] = ls;
        }
    }
    __syncthreads();
    if (tid < 128) {
        float s = sm_ps[tid * 4] + sm_ps[tid * 4 + 1] +
                  sm_ps[tid * 4 + 2] + sm_ps[tid * 4 + 3];
        g_pmax[(size_t)(bm + tid) * NT_TILES + blockIdx.x] = sm_max[tid];
        g_psum[(size_t)(bm + tid) * NT_TILES + blockIdx.x] = s;
    }
}

// ================= tf32 feature GEMM, fused attn dots, bf16 h output ======
#define MMA_PAD 36
#define MMA_STAGE_F (128 * MMA_PAD)
#define FEAT_SMEM_B (4 * MMA_STAGE_F * 4)
__global__ __launch_bounds__(256) void k_mma_feat(
    const float* __restrict__ Aext, const float* __restrict__ W,
    const float* __restrict__ asrc, const float* __restrict__ adst, int asel)
{
    extern __shared__ float smemf[];
    const float* A = asel ? g_hn : Aext;
    const int M = N_NODES, K = D;
    float* Abuf = smemf;
    float* Bbuf = smemf + 2 * MMA_STAGE_F;

    int tid = threadIdx.x;
    int warp = tid >> 5, lane = tid & 31;
    int wm = (warp & 1) * 64;
    int wnw = warp >> 1;
    int wn = wnw * 32;
    int bm = blockIdx.y * 128;

    float c[4][4][4];
#pragma unroll
    for (int mt = 0; mt < 4; mt++)
#pragma unroll
        for (int nt = 0; nt < 4; nt++)
#pragma unroll
            for (int r = 0; r < 4; r++) c[mt][nt][r] = 0.f;

    int gr = lane >> 2, gc = lane & 3;

    auto load_tile = [&](int it, int stage) {
        int k0 = it * 32;
        float* Ad = Abuf + stage * MMA_STAGE_F;
        float* Bd = Bbuf + stage * MMA_STAGE_F;
#pragma unroll
        for (int l = 0; l < 4; l++) {
            int linear = tid + l * 256;
            int row = linear >> 3;
            int kc = (linear & 7) * 4;
            int ar = bm + row;
            int okA = (ar < M);
            uint32_t sa = (uint32_t)__cvta_generic_to_shared(Ad + row * MMA_PAD + kc);
            cp_async16(sa, A + (size_t)(okA ? ar : 0) * K + k0 + kc, okA ? 16 : 0);
            uint32_t sb = (uint32_t)__cvta_generic_to_shared(Bd + row * MMA_PAD + kc);
            cp_async16(sb, W + (size_t)row * K + k0 + kc, 16);
        }
        cp_commit();
    };

    const int NIT = K / 32;
    load_tile(0, 0);
    for (int it = 0; it < NIT; it++) {
        int cur = it & 1;
        if (it + 1 < NIT) { load_tile(it + 1, cur ^ 1); cp_wait<1>(); }
        else cp_wait<0>();
        __syncthreads();

        const float* Ac = Abuf + cur * MMA_STAGE_F;
        const float* Bc = Bbuf + cur * MMA_STAGE_F;
#pragma unroll
        for (int ks = 0; ks < 4; ks++) {
            int kb = ks * 8;
            uint32_t a[4][4];
#pragma unroll
            for (int mt = 0; mt < 4; mt++) {
                int mrow = wm + mt * 16 + gr;
                a[mt][0] = __float_as_uint(Ac[mrow * MMA_PAD + kb + gc]);
                a[mt][1] = __float_as_uint(Ac[(mrow + 8) * MMA_PAD + kb + gc]);
                a[mt][2] = __float_as_uint(Ac[mrow * MMA_PAD + kb + gc + 4]);
                a[mt][3] = __float_as_uint(Ac[(mrow + 8) * MMA_PAD + kb + gc + 4]);
            }
            uint32_t b[4][2];
#pragma unroll
            for (int nt = 0; nt < 4; nt++) {
                int ncol = wn + nt * 8 + gr;
                b[nt][0] = __float_as_uint(Bc[ncol * MMA_PAD + kb + gc]);
                b[nt][1] = __float_as_uint(Bc[ncol * MMA_PAD + kb + gc + 4]);
            }
#pragma unroll
            for (int mt = 0; mt < 4; mt++)
#pragma unroll
                for (int nt = 0; nt < 4; nt++)
                    mma_tf32(c[mt][nt], a[mt][0], a[mt][1], a[mt][2], a[mt][3],
                             b[nt][0], b[nt][1]);
        }
        __syncthreads();
    }

    // epilogue: store bf16 h + fused attention dot partials
    float* sm_as = smemf;          // [128][4]
    float* sm_ad = smemf + 512;    // [128][4]

    int crow = lane >> 2, ccol = (lane & 3) * 2;
    float av[4][2], dv[4][2];
#pragma unroll
    for (int nt = 0; nt < 4; nt++)
#pragma unroll
        for (int j = 0; j < 2; j++) {
            int col = wn + nt * 8 + ccol + j;
            av[nt][j] = asrc[col];
            dv[nt][j] = adst[col];
        }

#pragma unroll
    for (int mt = 0; mt < 4; mt++) {
#pragma unroll
        for (int h = 0; h < 2; h++) {
            int lrow = wm + mt * 16 + crow + h * 8;
            int row = bm + lrow;
            float pas = 0.f, pad = 0.f;
            if (row < M) {
#pragma unroll
                for (int nt = 0; nt < 4; nt++) {
                    float v0 = c[mt][nt][h * 2];
                    float v1 = c[mt][nt][h * 2 + 1];
                    int col = wn + nt * 8 + ccol;
                    *(__nv_bfloat162*)(g_h16 + (size_t)row * D + col) =
                        __floats2bfloat162_rn(v0, v1);
                    pas += v0 * av[nt][0] + v1 * av[nt][1];
                    pad += v0 * dv[nt][0] + v1 * dv[nt][1];
                }
            }
            pas += __shfl_xor_sync(0xffffffff, pas, 1);
            pas += __shfl_xor_sync(0xffffffff, pas, 2);
            pad += __shfl_xor_sync(0xffffffff, pad, 1);
            pad += __shfl_xor_sync(0xffffffff, pad, 2);
            if ((lane & 3) == 0) {
                sm_as[lrow * 4 + wnw] = pas;
                sm_ad[lrow * 4 + wnw] = pad;
            }
        }
    }
    __syncthreads();
    if (tid < 128) {
        int row = bm + tid;
        if (row < M) {
            g_as[row] = sm_as[tid * 4] + sm_as[tid * 4 + 1] +
                        sm_as[tid * 4 + 2] + sm_as[tid * 4 + 3];
            g_ad[row] = sm_ad[tid * 4] + sm_ad[tid * 4 + 1] +
                        sm_ad[tid * 4 + 2] + sm_ad[tid * 4 + 3];
        }
    }
}

// ================= fp32 SGEMM lin1 with fused gather =================
__global__ __launch_bounds__(256) void k_sgemm_lin1(
    const int* __restrict__ x, const float* __restrict__ Bm,
    const float* __restrict__ bias)
{
    const int Nn = H3, K = H3;
    float* C = g_z1;

    __shared__ float As[8][128];
    __shared__ float Bs[8][128];

    int tid = threadIdx.x;
    int tx = tid & 15, ty = tid >> 4;
    int bm = blockIdx.y * 128, bn = blockIdx.x * 128;

    float acc[8][8];
#pragma unroll
    for (int i = 0; i < 8; i++)
#pragma unroll
        for (int j = 0; j < 8; j++) acc[i][j] = 0.f;

    int lr = tid >> 1;
    int lk = (tid & 1) * 4;

    for (int k0 = 0; k0 < K; k0 += 8) {
        int ar = bm + lr;
        int kidx = k0 + lk;
        int node = x[ar * 3 + (kidx >> 7)];
        float4 a4 = *(const float4*)(g_hn + (size_t)node * D + (kidx & 127));
        As[lk + 0][lr] = a4.x; As[lk + 1][lr] = a4.y;
        As[lk + 2][lr] = a4.z; As[lk + 3][lr] = a4.w;

        float4 b4 = make_float4(0.f, 0.f, 0.f, 0.f);
        int br = bn + lr;
        if (br < Nn) b4 = *(const float4*)(Bm + (size_t)br * K + kidx);
        Bs[lk + 0][lr] = b4.x; Bs[lk + 1][lr] = b4.y;
        Bs[lk + 2][lr] = b4.z; Bs[lk + 3][lr] = b4.w;
        __syncthreads();

#pragma unroll
        for (int k = 0; k < 8; k++) {
            float4 a0 = *(const float4*)&As[k][ty * 8];
            float4 a1 = *(const float4*)&As[k][ty * 8 + 4];
            float4 b0 = *(const float4*)&Bs[k][tx * 8];
            float4 b1 = *(const float4*)&Bs[k][tx * 8 + 4];
            float a[8] = {a0.x, a0.y, a0.z, a0.w, a1.x, a1.y, a1.z, a1.w};
            float b[8] = {b0.x, b0.y, b0.z, b0.w, b1.x, b1.y, b1.z, b1.w};
#pragma unroll
            for (int i = 0; i < 8; i++)
#pragma unroll
                for (int j = 0; j < 8; j++) acc[i][j] += a[i] * b[j];
        }
        __syncthreads();
    }

#pragma unroll
    for (int i = 0; i < 8; i++) {
        int row = bm + ty * 8 + i;
#pragma unroll
        for (int j = 0; j < 8; j++) {
            int col = bn + tx * 8 + j;
            if (col < Nn) C[(size_t)row * Nn + col] = acc[i][j] + bias[col];
        }
    }
}

// ================= LSE merge + subtract =================
__global__ void k_reduce_lse() {
    int row = blockIdx.x * 8 + (threadIdx.x >> 5);
    int lane = threadIdx.x & 31;
    const float* pm = g_pmax + (size_t)row * NT_TILES;
    const float* ps = g_psum + (size_t)row * NT_TILES;
    float M = NEG_INF;
    for (int i = lane; i < NT_TILES; i += 32) M = fmaxf(M, pm[i]);
#pragma unroll
    for (int o = 16; o; o >>= 1) M = fmaxf(M, __shfl_xor_sync(0xffffffff, M, o));
    float S = 0.f;
    for (int i = lane; i < NT_TILES; i += 32) S += ps[i] * __expf(pm[i] - M);
#pragma unroll
    for (int o = 16; o; o >>= 1) S += __shfl_xor_sync(0xffffffff, S, o);
    if (lane == 0) g_lse[row] = M + logf(S);
}

__global__ void k_sub_lse(float* __restrict__ out) {
    int idx = blockIdx.x * blockDim.x + threadIdx.x;
    if (idx >= BQ * 12500) return;
    int row = idx / 12500;
    float l = g_lse[row];
    float4* p = (float4*)out + idx;
    float4 v = *p;
    v.x -= l; v.y -= l; v.z -= l; v.w -= l;
    *p = v;
}

// ================= per-node attention aggregate (bf16 gather) =============
__global__ void k_node_attagg() {
    int gt = blockIdx.x * blockDim.x + threadIdx.x;
    int node = gt >> 5, lane = gt & 31;
    if (node >= N_NODES) return;
    int beg = g_off[node], end = g_off[node + 1];
    float ad = g_ad[node];

    float m = NEG_INF;
    for (int i = beg + lane; i < end; i += 32) {
        float s = g_as[g_srcl[i]] + ad;
        float e = (s > 0.f) ? s : 0.2f * s;
        g_e[i] = e;
        m = fmaxf(m, e);
    }
#pragma unroll
    for (int o = 16; o; o >>= 1) m = fmaxf(m, __shfl_xor_sync(0xffffffff, m, o));

    __syncwarp();
    float den = 0.f;
    for (int i = beg + lane; i < end; i += 32) {
        float ex = __expf(g_e[i] - m);
        g_e[i] = ex;
        den += ex;
    }
#pragma unroll
    for (int o = 16; o; o >>= 1) den += __shfl_xor_sync(0xffffffff, den, o);
    float inv = 1.f / den;
    __syncwarp();

    // each lane covers 4 columns (8 bytes bf16); gather 4 edges per iteration
    float4 acc = make_float4(0.f, 0.f, 0.f, 0.f);
    int coff = lane * 4;
    int i = beg;
    for (; i + 3 < end; i += 4) {
        float w0 = g_e[i] * inv,     w1 = g_e[i + 1] * inv;
        float w2 = g_e[i + 2] * inv, w3 = g_e[i + 3] * inv;
        int s0 = g_srcl[i],     s1 = g_srcl[i + 1];
        int s2 = g_srcl[i + 2], s3 = g_srcl[i + 3];
        uint2 p0 = *(const uint2*)(g_h16 + (size_t)s0 * D + coff);
        uint2 p1 = *(const uint2*)(g_h16 + (size_t)s1 * D + coff);
        uint2 p2 = *(const uint2*)(g_h16 + (size_t)s2 * D + coff);
        uint2 p3 = *(const uint2*)(g_h16 + (size_t)s3 * D + coff);
        float2 a0 = __bfloat1622float2(*(__nv_bfloat162*)&p0.x);
        float2 b0 = __bfloat1622float2(*(__nv_bfloat162*)&p0.y);
        float2 a1 = __bfloat1622float2(*(__nv_bfloat162*)&p1.x);
        float2 b1 = __bfloat1622float2(*(__nv_bfloat162*)&p1.y);
        float2 a2 = __bfloat1622float2(*(__nv_bfloat162*)&p2.x);
        float2 b2 = __bfloat1622float2(*(__nv_bfloat162*)&p2.y);
        float2 a3 = __bfloat1622float2(*(__nv_bfloat162*)&p3.x);
        float2 b3 = __bfloat1622float2(*(__nv_bfloat162*)&p3.y);
        acc.x += w0 * a0.x + w1 * a1.x + w2 * a2.x + w3 * a3.x;
        acc.y += w0 * a0.y + w1 * a1.y + w2 * a2.y + w3 * a3.y;
        acc.z += w0 * b0.x + w1 * b1.x + w2 * b2.x + w3 * b3.x;
        acc.w += w0 * b0.y + w1 * b1.y + w2 * b2.y + w3 * b3.y;
    }
    for (; i < end; i++) {
        float w = g_e[i] * inv;
        int s = g_srcl[i];
        uint2 p = *(const uint2*)(g_h16 + (size_t)s * D + coff);
        float2 a = __bfloat1622float2(*(__nv_bfloat162*)&p.x);
        float2 b = __bfloat1622float2(*(__nv_bfloat162*)&p.y);
        acc.x += w * a.x; acc.y += w * a.y;
        acc.z += w * b.x; acc.w += w * b.y;
    }
    *(float4*)(g_agg + (size_t)node * D + coff) = acc;
}

// ================= GraphNorm =================
#define RPB 64
__global__ void k_colstats(int layer) {
    int col = threadIdx.x;
    int r0 = blockIdx.x * RPB;
    int r1 = min(r0 + RPB, N_NODES);
    float s = 0.f, s2 = 0.f;
    for (int r = r0; r < r1; r++) {
        float a = g_agg[(size_t)r * D + col];
        s += a; s2 += a * a;
    }
    atomicAdd(&g_musum2[layer * D + col], s);
    atomicAdd(&g_varsum2[layer * D + col], s2);
}
__global__ void k_normalize(const float* __restrict__ bb, const float* __restrict__ gw,
                            const float* __restrict__ gb, const float* __restrict__ ms,
                            int layer) {
    int idx = blockIdx.x * blockDim.x + threadIdx.x;
    if (idx >= N_NODES * D) return;
    int d = idx & (D - 1);
    float S1 = g_musum2[layer * D + d] * (1.f / N_NODES);
    float S2 = g_varsum2[layer * D + d] * (1.f / N_NODES);
    float bv = bb[d];
    float mu = S1 + bv;
    float cc = bv - mu * ms[d];
    float var = S2 + 2.f * cc * S1 + cc * cc;
    float istd = rsqrtf(var + EPSV);
    float t = g_agg[idx] + cc;
    float v = t * istd * gw[d] + gb[d];
    g_hn[idx] = v > 0.f ? v : 0.f;
}

// ================= head BN =================
__global__ void k_bn_relu(const float* __restrict__ bw, const float* __restrict__ bb) {
    int c = blockIdx.x;
    int t = threadIdx.x;
    __shared__ float sm[256], ss[256];
    float s = 0.f, s2 = 0.f;
    for (int r = t; r < BQ; r += 256) {
        float v = g_z1[r * H3 + c];
        s += v; s2 += v * v;
    }
    sm[t] = s; ss[t] = s2;
    __syncthreads();
    for (int o = 128; o; o >>= 1) {
        if (t < o) { sm[t] += sm[t + o]; ss[t] += ss[t + o]; }
        __syncthreads();
    }
    float mu = sm[0] * (1.f / BQ);
    float var = ss[0] * (1.f / BQ) - mu * mu;
    float istd = rsqrtf(var + EPSV);
    float w = bw[c], bias = bb[c];
    for (int r = t; r < BQ; r += 256) {
        float v = (g_z1[r * H3 + c] - mu) * istd * w + bias;
        g_z16[r * H3 + c] = __float2bfloat16(v > 0.f ? v : 0.f);
    }
}

// ================= host driver =================
extern "C" void kernel_launch(void* const* d_in, const int* in_sizes, int n_in,
                              void* d_out, int out_size)
{
    const int*   x       = (const int*)  d_in[0];
    const int*   ei      = (const int*)  d_in[1];
    const float* emb     = (const float*)d_in[2];
    const float* W1      = (const float*)d_in[3];
    const float* asrc1   = (const float*)d_in[4];
    const float* adst1   = (const float*)d_in[5];
    const float* b1      = (const float*)d_in[6];
    const float* gn1w    = (const float*)d_in[7];
    const float* gn1b    = (const float*)d_in[8];
    const float* gn1ms   = (const float*)d_in[9];
    const float* W2      = (const float*)d_in[10];
    const float* asrc2   = (const float*)d_in[11];
    const float* adst2   = (const float*)d_in[12];
    const float* b2      = (const float*)d_in[13];
    const float* gn2w    = (const float*)d_in[14];
    const float* gn2b    = (const float*)d_in[15];
    const float* gn2ms   = (const float*)d_in[16];
    const float* lin1W   = (const float*)d_in[17];
    const float* lin1b   = (const float*)d_in[18];
    const float* bnw     = (const float*)d_in[19];
    const float* bnb     = (const float*)d_in[20];
    const float* lin2W   = (const float*)d_in[21];
    const float* lin2b   = (const float*)d_in[22];
    float* out = (float*)d_out;

    cudaFuncSetAttribute(k_mma_lin2, cudaFuncAttributeMaxDynamicSharedMemorySize, LIN2_SMEM_B);
    cudaFuncSetAttribute(k_mma_feat, cudaFuncAttributeMaxDynamicSharedMemorySize, FEAT_SMEM_B);

    dim3 gf(1, NT_TILES);

    k_cvt_w<<<(N_NODES * H3 / 4 + 255) / 256, 256>>>(lin2W);
    k_zero_deg<<<(N_NODES + 255) / 256, 256>>>();
    k_count<<<(ET + 255) / 256, 256>>>(ei);
    k_bsums<<<NB_SCAN, 256>>>();
    k_scan2<<<1, 256>>>();
    k_mma_feat<<<gf, 256, FEAT_SMEM_B>>>(emb, W1, asrc1, adst1, 0);
    k_addback<<<NB_SCAN, 256>>>();
    k_fill<<<(ET + 255) / 256, 256>>>(ei);

    // --- layer 1 rest ---
    k_node_attagg<<<(N_NODES * 32 + 255) / 256, 256>>>();
    k_colstats<<<(N_NODES + RPB - 1) / RPB, D>>>(0);
    k_normalize<<<(N_NODES * D + 255) / 256, 256>>>(b1, gn1w, gn1b, gn1ms, 0);

    // --- layer 2 ---
    k_mma_feat<<<gf, 256, FEAT_SMEM_B>>>(nullptr, W2, asrc2, adst2, 1);
    k_node_attagg<<<(N_NODES * 32 + 255) / 256, 256>>>();
    k_colstats<<<(N_NODES + RPB - 1) / RPB, D>>>(1);
    k_normalize<<<(N_NODES * D + 255) / 256, 256>>>(b2, gn2w, gn2b, gn2ms, 1);

    // --- head ---
    dim3 gz1((H3 + 127) / 128, BQ / 128);
    k_sgemm_lin1<<<gz1, 256>>>(x, lin1W, lin1b);
    k_bn_relu<<<H3, 256>>>(bnw, bnb);
    dim3 gz2(NT_TILES, BQ / 128);
    k_mma_lin2<<<gz2, 256, LIN2_SMEM_B>>>(lin2b, out);
    k_reduce_lse<<<BQ / 8, 256>>>();
    k_sub_lse<<<(BQ * 12500 + 255) / 256, 256>>>(out);
}